// round 3
// baseline (speedup 1.0000x reference)
#include <cuda_runtime.h>
#include <math.h>

// Problem constants
#define BB   4
#define CI   256
#define CO   256
#define HH   64
#define WWD  64
#define HWSZ (HH*WWD)
#define KKT  9

typedef unsigned long long u64;

// ---------------- scratch (device globals; no allocation) ----------------
__device__ float  g_xt[BB*HWSZ*CI];       // x in NHWC   (16.8 MB)
__device__ float  g_wtd[KKT*CI*2*CO];     // dcn weights [k][c][2o dup] (4.7 MB)
__device__ float  g_wtod[KKT*CI*64];      // offset weights [k][c][2oc dup, 32 padded]
__device__ float4 g_pw[BB*KKT*HWSZ];      // premasked bilinear weights
__device__ int4   g_po[BB*KKT*HWSZ];      // clamped corner element offsets

// ---------------- helpers ----------------
__device__ __forceinline__ void fma2(u64& d, u64 a, u64 b) {
    asm("fma.rn.f32x2 %0, %1, %2, %0;" : "+l"(d) : "l"(a), "l"(b));
}
__device__ __forceinline__ void unpk2(u64 v, float& lo, float& hi) {
    asm("mov.b64 {%0, %1}, %2;" : "=f"(lo), "=f"(hi) : "l"(v));
}
__device__ __forceinline__ void cp16(void* dst, const void* src) {
    unsigned d = (unsigned)__cvta_generic_to_shared(dst);
    asm volatile("cp.async.cg.shared.global [%0], [%1], 16;\n" :: "r"(d), "l"(src));
}
__device__ __forceinline__ void cp_commit() {
    asm volatile("cp.async.commit_group;\n" ::);
}
__device__ __forceinline__ void cp_wait0() {
    asm volatile("cp.async.wait_group 0;\n" ::: "memory");
}

// ---------------- kernel 1: NCHW -> NHWC transpose of x ----------------
__global__ void k_transpose_x(const float* __restrict__ x) {
    __shared__ float tile[32][33];
    int b  = blockIdx.z;
    int c0 = blockIdx.y * 32;
    int p0 = blockIdx.x * 32;
    int tx = threadIdx.x, ty = threadIdx.y;   // 32 x 8
    #pragma unroll
    for (int j = 0; j < 32; j += 8)
        tile[ty + j][tx] = x[((b*CI + c0 + ty + j)*HWSZ) + p0 + tx];
    __syncthreads();
    #pragma unroll
    for (int j = 0; j < 32; j += 8)
        g_xt[(b*HWSZ + p0 + ty + j)*CI + c0 + tx] = tile[tx][ty + j];
}

// ---------------- kernel 2: dcn_w [o][c][k] -> g_wtd [k][c][2o dup] ----------------
__global__ void k_transpose_wd(const float* __restrict__ dw) {
    int idx = blockIdx.x * 256 + threadIdx.x;
    if (idx < KKT*CI*CO) {
        int k = idx / (CI*CO);
        int r = idx % (CI*CO);
        int c = r >> 8;
        int o = r & 255;
        float v = dw[(o*CI + c)*KKT + k];
        g_wtd[(k*CI + c)*2*CO + 2*o]     = v;
        g_wtd[(k*CI + c)*2*CO + 2*o + 1] = v;
    }
}

// ---------------- kernel 2b: offset_w [oc][c][k] -> g_wtod [k][c][2oc dup padded] ----
__global__ void k_transpose_wod(const float* __restrict__ ow) {
    int idx = blockIdx.x * 256 + threadIdx.x;
    if (idx < KKT*CI*32) {
        int k = idx / (CI*32);
        int r = idx % (CI*32);
        int c = r >> 5;
        int n = r & 31;
        float v = (n < 27) ? ow[(n*CI + c)*KKT + k] : 0.0f;
        g_wtod[(k*CI + c)*64 + 2*n]     = v;
        g_wtod[(k*CI + c)*64 + 2*n + 1] = v;
    }
}

// ---------------- kernel 3: offset conv + param build ----------------
// grid 256 = (b,h). 128 threads. M=64 pixels (one row), N=32 (27 padded), K=9x256.
// 16-channel steps, double-buffered. f32x2 pairs = pixel pairs; B broadcast (dup'd).
__global__ __launch_bounds__(128) void k_offset(const float* __restrict__ ob) {
    __shared__ __align__(16) float sA[2][16][66];   // [buf][c][pix]
    __shared__ __align__(16) float sB[2][16][68];   // [buf][c][2n dup]
    __shared__ float so[64][33];                    // conv result [pix][oc]

    int tid  = threadIdx.x;
    int b    = blockIdx.x >> 6;
    int h    = blockIdx.x & 63;
    int wid  = tid >> 5;
    int lane = tid & 31;

    int apix = tid >> 1;          // A-build pixel (0..63)
    int acg  = (tid & 1) * 8;     // A-build channel base within 16-chunk
    int brow = tid >> 3;          // B-load row (0..15)
    int bcol = (tid & 7) * 4;     // B-load float col base

    u64 acc[8];
    #pragma unroll
    for (int j = 0; j < 8; ++j) acc[j] = 0ULL;

    // tap state
    bool valid;
    const float* asrc;
    {
        int y = h - 1, xx = apix - 1;   // tap 0: di=-1, dj=-1
        valid = (y >= 0) && (xx >= 0) && (xx < WWD);
        asrc = g_xt + (((size_t)(b*HWSZ) + (size_t)(y*WWD + xx)) * CI) + acg;
    }

    // prologue: A(0), B(0)
    {
        float4 f0 = make_float4(0,0,0,0), f1 = f0;
        if (valid) { f0 = *(const float4*)asrc; f1 = *(const float4*)(asrc + 4); }
        const float* bsrc = g_wtod + ((size_t)brow)*64 + bcol;   // tap 0, c0=0
        cp16(&sB[0][brow][bcol], bsrc);
        cp16(&sB[0][brow][bcol + 32], bsrc + 32);
        cp_commit();
        sA[0][acg+0][apix] = f0.x; sA[0][acg+1][apix] = f0.y;
        sA[0][acg+2][apix] = f0.z; sA[0][acg+3][apix] = f0.w;
        sA[0][acg+4][apix] = f1.x; sA[0][acg+5][apix] = f1.y;
        sA[0][acg+6][apix] = f1.z; sA[0][acg+7][apix] = f1.w;
        cp_wait0();
    }
    __syncthreads();

    #pragma unroll 1
    for (int s = 0; s < 144; ++s) {
        int buf = s & 1;
        float4 f0 = make_float4(0,0,0,0), f1 = f0;
        if (s < 143) {
            int sn = s + 1;
            if ((sn & 15) == 0) {
                int t = sn >> 4;
                int y = h + t/3 - 1, xx = apix + t%3 - 1;
                valid = (y >= 0) && (y < HH) && (xx >= 0) && (xx < WWD);
                asrc = g_xt + (((size_t)(b*HWSZ) + (size_t)(y*WWD + xx)) * CI) + acg;
            }
            int c0 = (sn & 15) * 16;
            if (valid) {
                const float* p = asrc + c0;
                f0 = *(const float4*)p; f1 = *(const float4*)(p + 4);
            }
            const float* bsrc = g_wtod + ((size_t)((sn >> 4)*CI + c0 + brow))*64 + bcol;
            cp16(&sB[buf^1][brow][bcol],      bsrc);
            cp16(&sB[buf^1][brow][bcol + 32], bsrc + 32);
            cp_commit();
        }
        // GEMM(s)
        #pragma unroll
        for (int cl = 0; cl < 16; ++cl) {
            u64 a = *(const u64*)&sA[buf][cl][2*lane];
            #pragma unroll
            for (int q = 0; q < 4; ++q) {
                ulonglong2 bb = *(const ulonglong2*)&sB[buf][cl][16*wid + 4*q];
                fma2(acc[2*q],     a, bb.x);
                fma2(acc[2*q + 1], a, bb.y);
            }
        }
        if (s < 143) {
            int nb = buf ^ 1;
            sA[nb][acg+0][apix] = f0.x; sA[nb][acg+1][apix] = f0.y;
            sA[nb][acg+2][apix] = f0.z; sA[nb][acg+3][apix] = f0.w;
            sA[nb][acg+4][apix] = f1.x; sA[nb][acg+5][apix] = f1.y;
            sA[nb][acg+6][apix] = f1.z; sA[nb][acg+7][apix] = f1.w;
            cp_wait0();
        }
        __syncthreads();
    }

    // scatter conv result: acc[j] = {pix 2l, pix 2l+1} for oc = 8*wid + j
    #pragma unroll
    for (int j = 0; j < 8; ++j) {
        float lo, hi;
        unpk2(acc[j], lo, hi);
        so[2*lane][8*wid + j]     = lo;
        so[2*lane + 1][8*wid + j] = hi;
    }
    __syncthreads();

    if (tid < 64) {
        float ov[27];
        #pragma unroll
        for (int oc = 0; oc < 27; ++oc) ov[oc] = so[tid][oc] + ob[oc];

        int w  = tid;
        int hw = h * WWD + w;
        #pragma unroll
        for (int kk = 0; kk < 9; ++kk) {
            float dy = ov[2*kk];
            float dx = ov[2*kk + 1];
            float m  = 1.0f / (1.0f + expf(-ov[18 + kk]));
            int ki = kk / 3, kj = kk % 3;
            float py = (float)(h - 1 + ki) + dy;
            float px = (float)(w - 1 + kj) + dx;
            float fy = floorf(py), fx = floorf(px);
            float wy = py - fy,    wx = px - fx;
            int y0 = (int)fy, x0 = (int)fx;
            int y1 = y0 + 1,  x1 = x0 + 1;

            bool vy0 = (y0 >= 0) && (y0 < HH);
            bool vy1 = (y1 >= 0) && (y1 < HH);
            bool vx0 = (x0 >= 0) && (x0 < WWD);
            bool vx1 = (x1 >= 0) && (x1 < WWD);

            float w00 = (1.0f - wy) * (1.0f - wx) * m * ((vy0 && vx0) ? 1.0f : 0.0f);
            float w01 = (1.0f - wy) * wx          * m * ((vy0 && vx1) ? 1.0f : 0.0f);
            float w10 = wy * (1.0f - wx)          * m * ((vy1 && vx0) ? 1.0f : 0.0f);
            float w11 = wy * wx                   * m * ((vy1 && vx1) ? 1.0f : 0.0f);

            int yc0 = min(max(y0, 0), HH - 1);
            int yc1 = min(max(y1, 0), HH - 1);
            int xc0 = min(max(x0, 0), WWD - 1);
            int xc1 = min(max(x1, 0), WWD - 1);

            int idx = ((b*KKT + kk)*HWSZ) + hw;
            g_pw[idx] = make_float4(w00, w01, w10, w11);
            g_po[idx] = make_int4((yc0*WWD + xc0)*CI, (yc0*WWD + xc1)*CI,
                                  (yc1*WWD + xc0)*CI, (yc1*WWD + xc1)*CI);
        }
    }
}

// ---------------- kernel 4: fused bilinear-sample + main GEMM ----------------
// grid 256 = (b,h). 256 threads. M=64 pixels, N=256, K=9x256 in 16-channel steps.
// f32x2 pairs = pixel pairs (A: one LDS.64/ch). B warp-uniform broadcast (dup'd).
struct __align__(16) SmemMain {
    float  Bd[2][16][520];   // [buf][c][2n dup + pad]
    float  A[2][16][66];     // [buf][c][pix + pad]
    float4 pw[2][64];        // param ring (tap parity)
    int4   po[2][64];
};

__global__ __launch_bounds__(256, 2) void k_main(float* __restrict__ out) {
    extern __shared__ char smem_raw[];
    SmemMain& S = *reinterpret_cast<SmemMain*>(smem_raw);

    int tid  = threadIdx.x;
    int bid  = blockIdx.x;
    int b    = bid >> 6;
    int h    = bid & 63;
    int hw0  = h * WWD;
    const float* xb = g_xt + (size_t)b * HWSZ * CI;

    int wid  = tid >> 5;          // warp -> n window [32*wid, 32*wid+32)
    int lane = tid & 31;          // lane -> pixel pair (2*lane, 2*lane+1)
    int gpix = tid >> 2;          // gather pixel (0..63)
    int gcg  = (tid & 3) * 4;     // gather channel base within 16-chunk
    int brr  = tid >> 4;          // B-load row (0..15)
    int brc  = (tid & 15) * 4;    // B-load float col base

    u64 acc[32];
    #pragma unroll
    for (int j = 0; j < 32; ++j) acc[j] = 0ULL;

    // preload params for taps 0 and 1
    if (tid < 128) {
        int t = tid >> 6;
        int pp = tid & 63;
        int pidx = ((b*KKT + t)*HWSZ) + hw0 + pp;
        S.pw[t][pp] = g_pw[pidx];
        S.po[t][pp] = g_po[pidx];
    }
    __syncthreads();

    // prologue: gather+blend+store A(0), load B(0)
    {
        float4 wv = S.pw[0][gpix];
        int4   po = S.po[0][gpix];
        const float* base = xb + gcg;
        float4 v0 = *(const float4*)(base + po.x);
        float4 v1 = *(const float4*)(base + po.y);
        float4 v2 = *(const float4*)(base + po.z);
        float4 v3 = *(const float4*)(base + po.w);
        const float* bsrc = g_wtd + ((size_t)brr)*512 + brc;   // tap 0, c0=0
        float* bdst = &S.Bd[0][brr][brc];
        #pragma unroll
        for (int q = 0; q < 8; ++q) cp16(bdst + q*64, bsrc + q*64);
        cp_commit();
        float s0 = wv.x*v0.x + wv.y*v1.x + wv.z*v2.x + wv.w*v3.x;
        float s1 = wv.x*v0.y + wv.y*v1.y + wv.z*v2.y + wv.w*v3.y;
        float s2 = wv.x*v0.z + wv.y*v1.z + wv.z*v2.z + wv.w*v3.z;
        float s3 = wv.x*v0.w + wv.y*v1.w + wv.z*v2.w + wv.w*v3.w;
        S.A[0][gcg+0][gpix] = s0; S.A[0][gcg+1][gpix] = s1;
        S.A[0][gcg+2][gpix] = s2; S.A[0][gcg+3][gpix] = s3;
        cp_wait0();
    }
    __syncthreads();

    #pragma unroll 1
    for (int s = 0; s < 144; ++s) {
        int buf = s & 1;

        // param ring prefetch: tap (s>>4)+1 at tap boundaries
        if ((s & 15) == 0 && s >= 16 && s <= 112 && tid < 64) {
            int t = (s >> 4) + 1;
            int pidx = ((b*KKT + t)*HWSZ) + hw0 + tid;
            S.pw[t & 1][tid] = g_pw[pidx];
            S.po[t & 1][tid] = g_po[pidx];
        }

        // gather A(s+1) into regs (held across GEMM); cp.async B(s+1)
        float4 v0, v1, v2, v3;
        if (s < 143) {
            int sn = s + 1;
            int slot = (sn >> 4) & 1;
            int4 po = S.po[slot][gpix];
            const float* base = xb + (sn & 15)*16 + gcg;
            v0 = *(const float4*)(base + po.x);
            v1 = *(const float4*)(base + po.y);
            v2 = *(const float4*)(base + po.z);
            v3 = *(const float4*)(base + po.w);
            const float* bsrc = g_wtd + ((size_t)((sn >> 4)*CI + (sn & 15)*16 + brr))*512 + brc;
            float* bdst = &S.Bd[buf^1][brr][brc];
            #pragma unroll
            for (int q = 0; q < 8; ++q) cp16(bdst + q*64, bsrc + q*64);
            cp_commit();
        }

        // GEMM(s): per channel, 1 LDS.64 A-pair + 16 broadcast LDS.128 B + 32 fma2
        #pragma unroll
        for (int cl = 0; cl < 16; ++cl) {
            u64 a = *(const u64*)&S.A[buf][cl][2*lane];
            const float* brow = &S.Bd[buf][cl][64*wid];
            #pragma unroll
            for (int q = 0; q < 8; ++q) {
                ulonglong2 bb = *(const ulonglong2*)(brow + 8*q);
                fma2(acc[4*q],     a, bb.x);
                fma2(acc[4*q + 1], a, bb.y);
                ulonglong2 bc = *(const ulonglong2*)(brow + 8*q + 4);
                fma2(acc[4*q + 2], a, bc.x);
                fma2(acc[4*q + 3], a, bc.y);
            }
        }

        // blend + store A(s+1), wait B
        if (s < 143) {
            int sn = s + 1;
            int slot = (sn >> 4) & 1;
            float4 wv = S.pw[slot][gpix];
            float s0 = wv.x*v0.x + wv.y*v1.x + wv.z*v2.x + wv.w*v3.x;
            float s1 = wv.x*v0.y + wv.y*v1.y + wv.z*v2.y + wv.w*v3.y;
            float s2 = wv.x*v0.z + wv.y*v1.z + wv.z*v2.z + wv.w*v3.z;
            float s3 = wv.x*v0.w + wv.y*v1.w + wv.z*v2.w + wv.w*v3.w;
            int nb = buf ^ 1;
            S.A[nb][gcg+0][gpix] = s0; S.A[nb][gcg+1][gpix] = s1;
            S.A[nb][gcg+2][gpix] = s2; S.A[nb][gcg+3][gpix] = s3;
            cp_wait0();
        }
        __syncthreads();
    }

    // epilogue: acc[j] = {out[p0][n], out[p1][n]}, n = 32*wid + j -> float2 store
    {
        float* op = out + ((size_t)(b*CO))*HWSZ + hw0 + 2*lane;
        int nbase = 32 * wid;
        #pragma unroll
        for (int j = 0; j < 32; ++j) {
            *(u64*)(op + (size_t)(nbase + j)*HWSZ) = acc[j];
        }
    }
}

// ---------------- launch ----------------
extern "C" void kernel_launch(void* const* d_in, const int* in_sizes, int n_in,
                              void* d_out, int out_size) {
    (void)in_sizes; (void)n_in; (void)out_size;
    const float* x  = (const float*)d_in[0];   // (4,256,64,64)
    const float* ow = (const float*)d_in[1];   // (27,256,3,3)
    const float* ob = (const float*)d_in[2];   // (27,)
    const float* dw = (const float*)d_in[3];   // (256,256,3,3)
    float* out = (float*)d_out;                // (4,256,64,64)

    cudaFuncSetAttribute(k_main, cudaFuncAttributeMaxDynamicSharedMemorySize,
                         (int)sizeof(SmemMain));

    dim3 tb(32, 8);
    dim3 tg(HWSZ/32, CI/32, BB);
    k_transpose_x<<<tg, tb>>>(x);
    k_transpose_wd<<<(KKT*CI*CO + 255)/256, 256>>>(dw);
    k_transpose_wod<<<(KKT*CI*32 + 255)/256, 256>>>(ow);
    k_offset<<<256, 128>>>(ob);
    k_main<<<256, 256, sizeof(SmemMain)>>>(out);
}

// round 5
// speedup vs baseline: 1.1057x; 1.1057x over previous
#include <cuda_runtime.h>
#include <math.h>
#include <stdint.h>

// Problem constants
#define BB   4
#define CI   256
#define CO   256
#define HH   64
#define WWD  64
#define HWSZ (HH*WWD)
#define KKT  9

typedef unsigned long long u64;

// ---------------- scratch (device globals; no allocation) ----------------
__device__ float  g_xt[BB*HWSZ*CI];       // x in NHWC   (16.8 MB)
__device__ float  g_wt[KKT*CI*CO];        // dcn weights [k][c][o] (2.36 MB)
__device__ float  g_wtod[KKT*CI*64];      // offset weights [k][c][2oc dup, 32 padded]
__device__ float4 g_pw[BB*KKT*HWSZ];      // premasked bilinear weights
__device__ int4   g_po[BB*KKT*HWSZ];      // clamped corner element offsets

// ---------------- helpers ----------------
__device__ __forceinline__ void fma2(u64& d, u64 a, u64 b) {
    asm("fma.rn.f32x2 %0, %1, %2, %0;" : "+l"(d) : "l"(a), "l"(b));
}
__device__ __forceinline__ void unpk2(u64 v, float& lo, float& hi) {
    asm("mov.b64 {%0, %1}, %2;" : "=f"(lo), "=f"(hi) : "l"(v));
}
__device__ __forceinline__ void cp16(void* dst, const void* src) {
    unsigned d = (unsigned)__cvta_generic_to_shared(dst);
    asm volatile("cp.async.cg.shared.global [%0], [%1], 16;\n" :: "r"(d), "l"(src));
}
__device__ __forceinline__ void cp_commit() {
    asm volatile("cp.async.commit_group;\n" ::);
}
__device__ __forceinline__ void cp_wait0() {
    asm volatile("cp.async.wait_group 0;\n" ::: "memory");
}

// ---------------- kernel 1: NCHW -> NHWC transpose of x ----------------
__global__ void k_transpose_x(const float* __restrict__ x) {
    __shared__ float tile[32][33];
    int b  = blockIdx.z;
    int c0 = blockIdx.y * 32;
    int p0 = blockIdx.x * 32;
    int tx = threadIdx.x, ty = threadIdx.y;   // 32 x 8
    #pragma unroll
    for (int j = 0; j < 32; j += 8)
        tile[ty + j][tx] = x[((b*CI + c0 + ty + j)*HWSZ) + p0 + tx];
    __syncthreads();
    #pragma unroll
    for (int j = 0; j < 32; j += 8)
        g_xt[(b*HWSZ + p0 + ty + j)*CI + c0 + tx] = tile[tx][ty + j];
}

// ---------------- kernel 2: dcn_w [o][c][k] -> g_wt [k][c][o] ----------------
__global__ void k_transpose_w(const float* __restrict__ dw) {
    int idx = blockIdx.x * 256 + threadIdx.x;
    if (idx < KKT*CI*CO) {
        int k = idx / (CI*CO);
        int r = idx % (CI*CO);
        int c = r >> 8;
        int o = r & 255;
        g_wt[idx] = dw[(o*CI + c)*KKT + k];
    }
}

// ---------------- kernel 2b: offset_w [oc][c][k] -> g_wtod [k][c][2oc dup padded] ----
__global__ void k_transpose_wod(const float* __restrict__ ow) {
    int idx = blockIdx.x * 256 + threadIdx.x;
    if (idx < KKT*CI*32) {
        int k = idx / (CI*32);
        int r = idx % (CI*32);
        int c = r >> 5;
        int n = r & 31;
        float v = (n < 27) ? ow[(n*CI + c)*KKT + k] : 0.0f;
        g_wtod[(k*CI + c)*64 + 2*n]     = v;
        g_wtod[(k*CI + c)*64 + 2*n + 1] = v;
    }
}

// ---------------- kernel 3: offset conv + param build (round-3, measured 148us) -------
__global__ __launch_bounds__(128) void k_offset(const float* __restrict__ ob) {
    __shared__ __align__(16) float sA[2][16][66];   // [buf][c][pix]
    __shared__ __align__(16) float sB[2][16][68];   // [buf][c][2n dup]
    __shared__ float so[64][33];                    // conv result [pix][oc]

    int tid  = threadIdx.x;
    int b    = blockIdx.x >> 6;
    int h    = blockIdx.x & 63;
    int wid  = tid >> 5;
    int lane = tid & 31;

    int apix = tid >> 1;          // A-build pixel (0..63)
    int acg  = (tid & 1) * 8;     // A-build channel base within 16-chunk
    int brow = tid >> 3;          // B-load row (0..15)
    int bcol = (tid & 7) * 4;     // B-load float col base

    u64 acc[8];
    #pragma unroll
    for (int j = 0; j < 8; ++j) acc[j] = 0ULL;

    bool valid;
    const float* asrc;
    {
        int y = h - 1, xx = apix - 1;   // tap 0
        valid = (y >= 0) && (xx >= 0) && (xx < WWD);
        asrc = g_xt + (((size_t)(b*HWSZ) + (size_t)(y*WWD + xx)) * CI) + acg;
    }

    {
        float4 f0 = make_float4(0,0,0,0), f1 = f0;
        if (valid) { f0 = *(const float4*)asrc; f1 = *(const float4*)(asrc + 4); }
        const float* bsrc = g_wtod + ((size_t)brow)*64 + bcol;
        cp16(&sB[0][brow][bcol], bsrc);
        cp16(&sB[0][brow][bcol + 32], bsrc + 32);
        cp_commit();
        sA[0][acg+0][apix] = f0.x; sA[0][acg+1][apix] = f0.y;
        sA[0][acg+2][apix] = f0.z; sA[0][acg+3][apix] = f0.w;
        sA[0][acg+4][apix] = f1.x; sA[0][acg+5][apix] = f1.y;
        sA[0][acg+6][apix] = f1.z; sA[0][acg+7][apix] = f1.w;
        cp_wait0();
    }
    __syncthreads();

    #pragma unroll 1
    for (int s = 0; s < 144; ++s) {
        int buf = s & 1;
        float4 f0 = make_float4(0,0,0,0), f1 = f0;
        if (s < 143) {
            int sn = s + 1;
            if ((sn & 15) == 0) {
                int t = sn >> 4;
                int y = h + t/3 - 1, xx = apix + t%3 - 1;
                valid = (y >= 0) && (y < HH) && (xx >= 0) && (xx < WWD);
                asrc = g_xt + (((size_t)(b*HWSZ) + (size_t)(y*WWD + xx)) * CI) + acg;
            }
            int c0 = (sn & 15) * 16;
            if (valid) {
                const float* p = asrc + c0;
                f0 = *(const float4*)p; f1 = *(const float4*)(p + 4);
            }
            const float* bsrc = g_wtod + ((size_t)((sn >> 4)*CI + c0 + brow))*64 + bcol;
            cp16(&sB[buf^1][brow][bcol],      bsrc);
            cp16(&sB[buf^1][brow][bcol + 32], bsrc + 32);
            cp_commit();
        }
        #pragma unroll
        for (int cl = 0; cl < 16; ++cl) {
            u64 a = *(const u64*)&sA[buf][cl][2*lane];
            #pragma unroll
            for (int q = 0; q < 4; ++q) {
                ulonglong2 bb = *(const ulonglong2*)&sB[buf][cl][16*wid + 4*q];
                fma2(acc[2*q],     a, bb.x);
                fma2(acc[2*q + 1], a, bb.y);
            }
        }
        if (s < 143) {
            int nb = buf ^ 1;
            sA[nb][acg+0][apix] = f0.x; sA[nb][acg+1][apix] = f0.y;
            sA[nb][acg+2][apix] = f0.z; sA[nb][acg+3][apix] = f0.w;
            sA[nb][acg+4][apix] = f1.x; sA[nb][acg+5][apix] = f1.y;
            sA[nb][acg+6][apix] = f1.z; sA[nb][acg+7][apix] = f1.w;
            cp_wait0();
        }
        __syncthreads();
    }

    #pragma unroll
    for (int j = 0; j < 8; ++j) {
        float lo, hi;
        unpk2(acc[j], lo, hi);
        so[2*lane][8*wid + j]     = lo;
        so[2*lane + 1][8*wid + j] = hi;
    }
    __syncthreads();

    if (tid < 64) {
        float ov[27];
        #pragma unroll
        for (int oc = 0; oc < 27; ++oc) ov[oc] = so[tid][oc] + ob[oc];

        int w  = tid;
        int hw = h * WWD + w;
        #pragma unroll
        for (int kk = 0; kk < 9; ++kk) {
            float dy = ov[2*kk];
            float dx = ov[2*kk + 1];
            float m  = 1.0f / (1.0f + expf(-ov[18 + kk]));
            int ki = kk / 3, kj = kk % 3;
            float py = (float)(h - 1 + ki) + dy;
            float px = (float)(w - 1 + kj) + dx;
            float fy = floorf(py), fx = floorf(px);
            float wy = py - fy,    wx = px - fx;
            int y0 = (int)fy, x0 = (int)fx;
            int y1 = y0 + 1,  x1 = x0 + 1;

            bool vy0 = (y0 >= 0) && (y0 < HH);
            bool vy1 = (y1 >= 0) && (y1 < HH);
            bool vx0 = (x0 >= 0) && (x0 < WWD);
            bool vx1 = (x1 >= 0) && (x1 < WWD);

            float w00 = (1.0f - wy) * (1.0f - wx) * m * ((vy0 && vx0) ? 1.0f : 0.0f);
            float w01 = (1.0f - wy) * wx          * m * ((vy0 && vx1) ? 1.0f : 0.0f);
            float w10 = wy * (1.0f - wx)          * m * ((vy1 && vx0) ? 1.0f : 0.0f);
            float w11 = wy * wx                   * m * ((vy1 && vx1) ? 1.0f : 0.0f);

            int yc0 = min(max(y0, 0), HH - 1);
            int yc1 = min(max(y1, 0), HH - 1);
            int xc0 = min(max(x0, 0), WWD - 1);
            int xc1 = min(max(x1, 0), WWD - 1);

            int idx = ((b*KKT + kk)*HWSZ) + hw;
            g_pw[idx] = make_float4(w00, w01, w10, w11);
            g_po[idx] = make_int4((yc0*WWD + xc0)*CI, (yc0*WWD + xc1)*CI,
                                  (yc1*WWD + xc0)*CI, (yc1*WWD + xc1)*CI);
        }
    }
}

// ---------------- kernel 4: fused bilinear-sample + main GEMM (512 threads) ----------
// grid 256 = (b,h). M=64 pixels, N=256, K=2304 in 72 steps of 32 channels.
// f32x2 pairs over n (B natural pairs, NOT duplicated); A duplicated in smem only.
// Thread tile: 2 pixels x 16 n -> 16 u64 acc (32 regs). Warp: 32 pixels x 32 n.
struct __align__(16) SmemMain {
    float  A[2][32][132];    // [buf][c][2*pix dup + pad]     33 KB
    float  Bs[2][32][264];   // [buf][c][n + pad]             66 KB
    float4 pw[2][64];        // param ring (tap parity)
    int4   po[2][64];
};

__global__ __launch_bounds__(512, 1) void k_main(float* __restrict__ out) {
    extern __shared__ char smem_raw[];
    SmemMain& S = *reinterpret_cast<SmemMain*>(smem_raw);

    int tid  = threadIdx.x;
    int b    = blockIdx.x >> 6;
    int h    = blockIdx.x & 63;
    int hw0  = h * WWD;
    const float* xb = g_xt + (size_t)b * HWSZ * CI;

    // GEMM mapping
    int wid  = tid >> 5;
    int lane = tid & 31;
    int ph   = wid & 1;                       // pixel half (32 pixels)
    int nw   = (wid >> 1) * 32;               // warp n base
    int lp   = lane & 15;                     // pixel-pair index within half
    int npb  = nw + (lane >> 4) * 16;         // thread n base (16 n)
    int arow = 64*ph + 4*lp;                  // A float4 offset within row

    // A-build mapping: 64 pix x 32 ch / 512 thr = 4 ch per thread
    int gpix = tid >> 3;
    int gc   = (tid & 7) * 4;
    // B-load mapping: 32 rows x 256 cols / 512 thr = 16 floats per thread
    int br   = tid >> 4;
    int bc   = (tid & 15) * 16;

    u64 acc[2][8];
    #pragma unroll
    for (int i = 0; i < 2; ++i)
        #pragma unroll
        for (int j = 0; j < 8; ++j) acc[i][j] = 0ULL;

    // preload params for taps 0 and 1
    if (tid < 128) {
        int t = tid >> 6;
        int pp = tid & 63;
        int pidx = ((b*KKT + t)*HWSZ) + hw0 + pp;
        S.pw[t][pp] = g_pw[pidx];
        S.po[t][pp] = g_po[pidx];
    }
    __syncthreads();

    // prologue: build A(0) + load B(0) into buf 0
    {
        float4 wv = S.pw[0][gpix];
        int4   po = S.po[0][gpix];
        const float* base = xb + gc;
        float4 v0 = *(const float4*)(base + po.x);
        float4 v1 = *(const float4*)(base + po.y);
        float4 v2 = *(const float4*)(base + po.z);
        float4 v3 = *(const float4*)(base + po.w);
        const float* bsrc = g_wt + ((size_t)br)*CO + bc;   // tap 0, c0 = 0
        #pragma unroll
        for (int q = 0; q < 4; ++q) cp16(&S.Bs[0][br][bc + q*4], bsrc + q*4);
        cp_commit();
        float s0 = wv.x*v0.x + wv.y*v1.x + wv.z*v2.x + wv.w*v3.x;
        float s1 = wv.x*v0.y + wv.y*v1.y + wv.z*v2.y + wv.w*v3.y;
        float s2 = wv.x*v0.z + wv.y*v1.z + wv.z*v2.z + wv.w*v3.z;
        float s3 = wv.x*v0.w + wv.y*v1.w + wv.z*v2.w + wv.w*v3.w;
        *(float2*)&S.A[0][gc+0][2*gpix] = make_float2(s0, s0);
        *(float2*)&S.A[0][gc+1][2*gpix] = make_float2(s1, s1);
        *(float2*)&S.A[0][gc+2][2*gpix] = make_float2(s2, s2);
        *(float2*)&S.A[0][gc+3][2*gpix] = make_float2(s3, s3);
        cp_wait0();
    }
    __syncthreads();

    #pragma unroll 1
    for (int s = 0; s < 72; ++s) {
        int buf = s & 1;

        // param ring prefetch: tap (s>>3)+1 at tap boundaries (slot free, see analysis)
        if ((s & 7) == 0 && s >= 8 && s <= 56 && tid < 64) {
            int t = (s >> 3) + 1;
            int pidx = ((b*KKT + t)*HWSZ) + hw0 + tid;
            S.pw[t & 1][tid] = g_pw[pidx];
            S.po[t & 1][tid] = g_po[pidx];
        }

        // prefetch step s+1: gathers into regs (held over GEMM), B via cp.async
        float4 v0, v1, v2, v3;
        int slot = 0;
        if (s < 71) {
            int sn = s + 1;
            slot = (sn >> 3) & 1;
            int4 po = S.po[slot][gpix];
            const float* base = xb + (sn & 7)*32 + gc;
            v0 = *(const float4*)(base + po.x);
            v1 = *(const float4*)(base + po.y);
            v2 = *(const float4*)(base + po.z);
            v3 = *(const float4*)(base + po.w);
            const float* bsrc = g_wt + ((size_t)((sn >> 3)*CI + (sn & 7)*32 + br))*CO + bc;
            #pragma unroll
            for (int q = 0; q < 4; ++q) cp16(&S.Bs[buf^1][br][bc + q*4], bsrc + q*4);
            cp_commit();
        }

        // GEMM(s): per channel: 1 LDS.128 A (dup pairs) + 4 dedup LDS.128 B + 16 fma2
        #pragma unroll 8
        for (int cl = 0; cl < 32; ++cl) {
            float4 af = *(const float4*)&S.A[buf][cl][arow];
            u64 a0 = ((const u64*)&af)[0];    // {A[p0], A[p0]}
            u64 a1 = ((const u64*)&af)[1];    // {A[p1], A[p1]}
            const float* bp = &S.Bs[buf][cl][npb];
            ulonglong2 bq0 = *(const ulonglong2*)(bp);
            ulonglong2 bq1 = *(const ulonglong2*)(bp + 4);
            ulonglong2 bq2 = *(const ulonglong2*)(bp + 8);
            ulonglong2 bq3 = *(const ulonglong2*)(bp + 12);
            fma2(acc[0][0], a0, bq0.x); fma2(acc[1][0], a1, bq0.x);
            fma2(acc[0][1], a0, bq0.y); fma2(acc[1][1], a1, bq0.y);
            fma2(acc[0][2], a0, bq1.x); fma2(acc[1][2], a1, bq1.x);
            fma2(acc[0][3], a0, bq1.y); fma2(acc[1][3], a1, bq1.y);
            fma2(acc[0][4], a0, bq2.x); fma2(acc[1][4], a1, bq2.x);
            fma2(acc[0][5], a0, bq2.y); fma2(acc[1][5], a1, bq2.y);
            fma2(acc[0][6], a0, bq3.x); fma2(acc[1][6], a1, bq3.x);
            fma2(acc[0][7], a0, bq3.y); fma2(acc[1][7], a1, bq3.y);
        }

        // blend + store A(s+1), wait for B(s+1)
        if (s < 71) {
            float4 wv = S.pw[slot][gpix];
            float s0 = wv.x*v0.x + wv.y*v1.x + wv.z*v2.x + wv.w*v3.x;
            float s1 = wv.x*v0.y + wv.y*v1.y + wv.z*v2.y + wv.w*v3.y;
            float s2 = wv.x*v0.z + wv.y*v1.z + wv.z*v2.z + wv.w*v3.z;
            float s3 = wv.x*v0.w + wv.y*v1.w + wv.z*v2.w + wv.w*v3.w;
            int nb = buf ^ 1;
            *(float2*)&S.A[nb][gc+0][2*gpix] = make_float2(s0, s0);
            *(float2*)&S.A[nb][gc+1][2*gpix] = make_float2(s1, s1);
            *(float2*)&S.A[nb][gc+2][2*gpix] = make_float2(s2, s2);
            *(float2*)&S.A[nb][gc+3][2*gpix] = make_float2(s3, s3);
            cp_wait0();
        }
        __syncthreads();
    }

    // epilogue: acc[i][j] = {out[n][p_i], out[n+1][p_i]}, n = npb + 2j
    {
        float* op = out + ((size_t)(b*CO))*HWSZ + hw0;
        int p0 = 32*ph + 2*lp;
        #pragma unroll
        for (int j = 0; j < 8; ++j) {
            int n = npb + 2*j;
            float lo, hi;
            unpk2(acc[0][j], lo, hi);
            op[(size_t)n*HWSZ + p0]       = lo;
            op[(size_t)(n+1)*HWSZ + p0]   = hi;
            unpk2(acc[1][j], lo, hi);
            op[(size_t)n*HWSZ + p0 + 1]     = lo;
            op[(size_t)(n+1)*HWSZ + p0 + 1] = hi;
        }
    }
}

// ---------------- launch ----------------
extern "C" void kernel_launch(void* const* d_in, const int* in_sizes, int n_in,
                              void* d_out, int out_size) {
    (void)in_sizes; (void)n_in; (void)out_size;
    const float* x  = (const float*)d_in[0];   // (4,256,64,64)
    const float* ow = (const float*)d_in[1];   // (27,256,3,3)
    const float* ob = (const float*)d_in[2];   // (27,)
    const float* dw = (const float*)d_in[3];   // (256,256,3,3)
    float* out = (float*)d_out;                // (4,256,64,64)

    cudaFuncSetAttribute(k_main, cudaFuncAttributeMaxDynamicSharedMemorySize,
                         (int)sizeof(SmemMain));

    dim3 tb(32, 8);
    dim3 tg(HWSZ/32, CI/32, BB);
    k_transpose_x<<<tg, tb>>>(x);
    k_transpose_w<<<(KKT*CI*CO + 255)/256, 256>>>(dw);
    k_transpose_wod<<<(KKT*CI*32 + 255)/256, 256>>>(ow);
    k_offset<<<256, 128>>>(ob);
    k_main<<<256, 512, sizeof(SmemMain)>>>(out);
}

// round 6
// speedup vs baseline: 2.1839x; 1.9752x over previous
#include <cuda_runtime.h>
#include <math.h>
#include <stdint.h>

// Problem constants
#define BB   4
#define CI   256
#define CO   256
#define HH   64
#define WWD  64
#define HWSZ (HH*WWD)
#define KKT  9
#define NCH  72            // K = 2304 in chunks of 32 channels

typedef unsigned long long u64;

// ---------------- scratch (device globals; no allocation) ----------------
__device__ float  g_xt[BB*HWSZ*CI];        // x in NHWC   (16.8 MB)
__device__ unsigned short g_Bh16[NCH*32*256];  // bf16 hi of dcn_w, [chunk][k32][n256]
__device__ unsigned short g_Bl16[NCH*32*256];  // bf16 lo
__device__ float  g_wtod[KKT*CI*64];       // offset weights [k][c][2oc dup, 32 padded]
__device__ float4 g_pw[BB*KKT*HWSZ];       // premasked bilinear weights
__device__ int4   g_po[BB*KKT*HWSZ];       // clamped corner element offsets

// ---------------- helpers ----------------
__device__ __forceinline__ void fma2(u64& d, u64 a, u64 b) {
    asm("fma.rn.f32x2 %0, %1, %2, %0;" : "+l"(d) : "l"(a), "l"(b));
}
__device__ __forceinline__ void unpk2(u64 v, float& lo, float& hi) {
    asm("mov.b64 {%0, %1}, %2;" : "=f"(lo), "=f"(hi) : "l"(v));
}
__device__ __forceinline__ void cp16(void* dst, const void* src) {
    unsigned d = (unsigned)__cvta_generic_to_shared(dst);
    asm volatile("cp.async.cg.shared.global [%0], [%1], 16;\n" :: "r"(d), "l"(src));
}
__device__ __forceinline__ void cp16u(uint32_t dst, const void* src) {
    asm volatile("cp.async.cg.shared.global [%0], [%1], 16;\n" :: "r"(dst), "l"(src));
}
__device__ __forceinline__ void cp_commit() {
    asm volatile("cp.async.commit_group;\n" ::);
}
__device__ __forceinline__ void cp_wait0() {
    asm volatile("cp.async.wait_group 0;\n" ::: "memory");
}
__device__ __forceinline__ uint32_t smem_u32(const void* p) {
    uint32_t r;
    asm("{ .reg .u64 t; cvta.to.shared.u64 t, %1; cvt.u32.u64 %0, t; }" : "=r"(r) : "l"(p));
    return r;
}
// pack {lo, hi} floats to bf16x2 (round-to-nearest)
__device__ __forceinline__ uint32_t bf16x2(float lo, float hi) {
    uint32_t r;
    asm("cvt.rn.bf16x2.f32 %0, %1, %2;" : "=r"(r) : "f"(hi), "f"(lo));
    return r;
}
__device__ __forceinline__ void ldm_x4(uint32_t* r, uint32_t addr) {
    asm volatile("ldmatrix.sync.aligned.m8n8.x4.shared.b16 {%0,%1,%2,%3}, [%4];"
        : "=r"(r[0]), "=r"(r[1]), "=r"(r[2]), "=r"(r[3]) : "r"(addr));
}
__device__ __forceinline__ void ldm_x4t(uint32_t* r, uint32_t addr) {
    asm volatile("ldmatrix.sync.aligned.m8n8.x4.trans.shared.b16 {%0,%1,%2,%3}, [%4];"
        : "=r"(r[0]), "=r"(r[1]), "=r"(r[2]), "=r"(r[3]) : "r"(addr));
}
__device__ __forceinline__ void mma_bf16(float* d, const uint32_t* a, const uint32_t* b) {
    asm volatile("mma.sync.aligned.m16n8k16.row.col.f32.bf16.bf16.f32 "
        "{%0,%1,%2,%3}, {%4,%5,%6,%7}, {%8,%9}, {%0,%1,%2,%3};"
        : "+f"(d[0]), "+f"(d[1]), "+f"(d[2]), "+f"(d[3])
        : "r"(a[0]), "r"(a[1]), "r"(a[2]), "r"(a[3]), "r"(b[0]), "r"(b[1]));
}

// ---------------- kernel 1: NCHW -> NHWC transpose of x ----------------
__global__ void k_transpose_x(const float* __restrict__ x) {
    __shared__ float tile[32][33];
    int b  = blockIdx.z;
    int c0 = blockIdx.y * 32;
    int p0 = blockIdx.x * 32;
    int tx = threadIdx.x, ty = threadIdx.y;   // 32 x 8
    #pragma unroll
    for (int j = 0; j < 32; j += 8)
        tile[ty + j][tx] = x[((b*CI + c0 + ty + j)*HWSZ) + p0 + tx];
    __syncthreads();
    #pragma unroll
    for (int j = 0; j < 32; j += 8)
        g_xt[(b*HWSZ + p0 + ty + j)*CI + c0 + tx] = tile[tx][ty + j];
}

// ---------------- kernel 2: dcn_w -> bf16 hi/lo chunk images [chunk][k32][n] --------
__global__ void k_prep_b(const float* __restrict__ dw) {
    int idx = blockIdx.x * 256 + threadIdx.x;
    if (idx >= NCH*8192) return;
    int kc = idx >> 13;
    int r  = idx & 8191;
    int k  = r >> 8;
    int n  = r & 255;
    int tap = kc >> 3;
    int c   = (kc & 7)*32 + k;
    float v = dw[(n*CI + c)*KKT + tap];
    uint32_t hp = bf16x2(v, 0.0f);
    float hf = __uint_as_float(hp << 16);
    uint32_t lp = bf16x2(v - hf, 0.0f);
    g_Bh16[idx] = (unsigned short)(hp & 0xffff);
    g_Bl16[idx] = (unsigned short)(lp & 0xffff);
}

// ---------------- kernel 2b: offset_w [oc][c][k] -> g_wtod [k][c][2oc dup padded] ----
__global__ void k_transpose_wod(const float* __restrict__ ow) {
    int idx = blockIdx.x * 256 + threadIdx.x;
    if (idx < KKT*CI*32) {
        int k = idx / (CI*32);
        int r = idx % (CI*32);
        int c = r >> 5;
        int n = r & 31;
        float v = (n < 27) ? ow[(n*CI + c)*KKT + k] : 0.0f;
        g_wtod[(k*CI + c)*64 + 2*n]     = v;
        g_wtod[(k*CI + c)*64 + 2*n + 1] = v;
    }
}

// ---------------- kernel 3: offset conv + param build (measured 148us, unchanged) ----
__global__ __launch_bounds__(128) void k_offset(const float* __restrict__ ob) {
    __shared__ __align__(16) float sA[2][16][66];
    __shared__ __align__(16) float sB[2][16][68];
    __shared__ float so[64][33];

    int tid  = threadIdx.x;
    int b    = blockIdx.x >> 6;
    int h    = blockIdx.x & 63;
    int wid  = tid >> 5;
    int lane = tid & 31;

    int apix = tid >> 1;
    int acg  = (tid & 1) * 8;
    int brow = tid >> 3;
    int bcol = (tid & 7) * 4;

    u64 acc[8];
    #pragma unroll
    for (int j = 0; j < 8; ++j) acc[j] = 0ULL;

    bool valid;
    const float* asrc;
    {
        int y = h - 1, xx = apix - 1;
        valid = (y >= 0) && (xx >= 0) && (xx < WWD);
        asrc = g_xt + (((size_t)(b*HWSZ) + (size_t)(y*WWD + xx)) * CI) + acg;
    }

    {
        float4 f0 = make_float4(0,0,0,0), f1 = f0;
        if (valid) { f0 = *(const float4*)asrc; f1 = *(const float4*)(asrc + 4); }
        const float* bsrc = g_wtod + ((size_t)brow)*64 + bcol;
        cp16(&sB[0][brow][bcol], bsrc);
        cp16(&sB[0][brow][bcol + 32], bsrc + 32);
        cp_commit();
        sA[0][acg+0][apix] = f0.x; sA[0][acg+1][apix] = f0.y;
        sA[0][acg+2][apix] = f0.z; sA[0][acg+3][apix] = f0.w;
        sA[0][acg+4][apix] = f1.x; sA[0][acg+5][apix] = f1.y;
        sA[0][acg+6][apix] = f1.z; sA[0][acg+7][apix] = f1.w;
        cp_wait0();
    }
    __syncthreads();

    #pragma unroll 1
    for (int s = 0; s < 144; ++s) {
        int buf = s & 1;
        float4 f0 = make_float4(0,0,0,0), f1 = f0;
        if (s < 143) {
            int sn = s + 1;
            if ((sn & 15) == 0) {
                int t = sn >> 4;
                int y = h + t/3 - 1, xx = apix + t%3 - 1;
                valid = (y >= 0) && (y < HH) && (xx >= 0) && (xx < WWD);
                asrc = g_xt + (((size_t)(b*HWSZ) + (size_t)(y*WWD + xx)) * CI) + acg;
            }
            int c0 = (sn & 15) * 16;
            if (valid) {
                const float* p = asrc + c0;
                f0 = *(const float4*)p; f1 = *(const float4*)(p + 4);
            }
            const float* bsrc = g_wtod + ((size_t)((sn >> 4)*CI + c0 + brow))*64 + bcol;
            cp16(&sB[buf^1][brow][bcol],      bsrc);
            cp16(&sB[buf^1][brow][bcol + 32], bsrc + 32);
            cp_commit();
        }
        #pragma unroll
        for (int cl = 0; cl < 16; ++cl) {
            u64 a = *(const u64*)&sA[buf][cl][2*lane];
            #pragma unroll
            for (int q = 0; q < 4; ++q) {
                ulonglong2 bb = *(const ulonglong2*)&sB[buf][cl][16*wid + 4*q];
                fma2(acc[2*q],     a, bb.x);
                fma2(acc[2*q + 1], a, bb.y);
            }
        }
        if (s < 143) {
            int nb = buf ^ 1;
            sA[nb][acg+0][apix] = f0.x; sA[nb][acg+1][apix] = f0.y;
            sA[nb][acg+2][apix] = f0.z; sA[nb][acg+3][apix] = f0.w;
            sA[nb][acg+4][apix] = f1.x; sA[nb][acg+5][apix] = f1.y;
            sA[nb][acg+6][apix] = f1.z; sA[nb][acg+7][apix] = f1.w;
            cp_wait0();
        }
        __syncthreads();
    }

    #pragma unroll
    for (int j = 0; j < 8; ++j) {
        float lo, hi;
        unpk2(acc[j], lo, hi);
        so[2*lane][8*wid + j]     = lo;
        so[2*lane + 1][8*wid + j] = hi;
    }
    __syncthreads();

    if (tid < 64) {
        float ov[27];
        #pragma unroll
        for (int oc = 0; oc < 27; ++oc) ov[oc] = so[tid][oc] + ob[oc];

        int w  = tid;
        int hw = h * WWD + w;
        #pragma unroll
        for (int kk = 0; kk < 9; ++kk) {
            float dy = ov[2*kk];
            float dx = ov[2*kk + 1];
            float m  = 1.0f / (1.0f + expf(-ov[18 + kk]));
            int ki = kk / 3, kj = kk % 3;
            float py = (float)(h - 1 + ki) + dy;
            float px = (float)(w - 1 + kj) + dx;
            float fy = floorf(py), fx = floorf(px);
            float wy = py - fy,    wx = px - fx;
            int y0 = (int)fy, x0 = (int)fx;
            int y1 = y0 + 1,  x1 = x0 + 1;

            bool vy0 = (y0 >= 0) && (y0 < HH);
            bool vy1 = (y1 >= 0) && (y1 < HH);
            bool vx0 = (x0 >= 0) && (x0 < WWD);
            bool vx1 = (x1 >= 0) && (x1 < WWD);

            float w00 = (1.0f - wy) * (1.0f - wx) * m * ((vy0 && vx0) ? 1.0f : 0.0f);
            float w01 = (1.0f - wy) * wx          * m * ((vy0 && vx1) ? 1.0f : 0.0f);
            float w10 = wy * (1.0f - wx)          * m * ((vy1 && vx0) ? 1.0f : 0.0f);
            float w11 = wy * wx                   * m * ((vy1 && vx1) ? 1.0f : 0.0f);

            int yc0 = min(max(y0, 0), HH - 1);
            int yc1 = min(max(y1, 0), HH - 1);
            int xc0 = min(max(x0, 0), WWD - 1);
            int xc1 = min(max(x1, 0), WWD - 1);

            int idx = ((b*KKT + kk)*HWSZ) + hw;
            g_pw[idx] = make_float4(w00, w01, w10, w11);
            g_po[idx] = make_int4((yc0*WWD + xc0)*CI, (yc0*WWD + xc1)*CI,
                                  (yc1*WWD + xc0)*CI, (yc1*WWD + xc1)*CI);
        }
    }
}

// ---------------- kernel 4: fused bilinear-sample + bf16x3 mma.sync GEMM -------------
// grid 256 = (b,h), 512 threads (16 warps). M=64 pix, N=256, K=2304 in 72 chunks of 32.
// Warp w: m-half (w&1)*32 pixels (2 m16 tiles), n-slice (w>>1)*32 (4 n8 tiles).
// SMEM byte offsets:
//  A planes  [split(2)][buf(2)] : 64 pix x 80B (32 bf16 + pad)      -> 4 x 5120
//  B planes  [split(2)][buf(2)] : 32 k x 528B (256 bf16 + pad)      -> 4 x 16896
//  pw / po rings: 2 slots x 64 x 16B each
#define MOF_A(s, f)  (((s)*2 + (f)) * 5120)
#define MOF_B(s, f)  (20480 + ((s)*2 + (f)) * 16896)
#define MOF_PW       88064
#define MOF_PO       90112
#define MSM_TOTAL    92160

__global__ __launch_bounds__(512, 1) void k_main(float* __restrict__ out) {
    extern __shared__ char sm[];
    uint32_t su = smem_u32(sm);

    int tid  = threadIdx.x;
    int lane = tid & 31;
    int wid  = tid >> 5;
    int b    = blockIdx.x >> 6;
    int h    = blockIdx.x & 63;
    int hw0  = h * WWD;
    const float* xb = g_xt + (size_t)b * HWSZ * CI;

    // warp GEMM mapping
    int mh = (wid & 1) * 32;          // pixel base
    int ns = (wid >> 1) * 32;         // n base
    int g  = lane >> 3, lr = lane & 7;
    int a_row = (g & 1)*8 + lr;       // row within m16 tile
    int a_cb  = (g >> 1) * 16;        // byte col offset within k16
    int b_krow = (g & 1)*8 + lr;      // k within k16
    int b_cb  = (g >> 1) * 16;        // byte col offset within n-pair

    // A-build mapping: 64 pix x 32 ch / 512 thr -> 4 ch per thread
    int gp = tid >> 3;
    int gk = (tid & 7) * 4;
    // B-load mapping: 2 splits x 32 rows x 512B / 512 thr -> 32B per split
    int br  = tid >> 4;
    int bsg = (tid & 15) * 32;

    float4* pwp = (float4*)(sm + MOF_PW);
    int4*   pop = (int4*)  (sm + MOF_PO);

    float acc[2][4][4];
    #pragma unroll
    for (int i = 0; i < 2; ++i)
        #pragma unroll
        for (int j = 0; j < 4; ++j)
            #pragma unroll
            for (int q = 0; q < 4; ++q) acc[i][j][q] = 0.0f;

    // preload params for taps 0 and 1
    if (tid < 128) {
        int t = tid >> 6;
        int pp = tid & 63;
        int pidx = ((b*KKT + t)*HWSZ) + hw0 + pp;
        pwp[t*64 + pp] = g_pw[pidx];
        pop[t*64 + pp] = g_po[pidx];
    }
    __syncthreads();

    // prologue: build chunk 0 into buf 0
    {
        float4 wv = pwp[gp];
        int4   po = pop[gp];
        const float* base = xb + gk;
        float4 v0 = *(const float4*)(base + po.x);
        float4 v1 = *(const float4*)(base + po.y);
        float4 v2 = *(const float4*)(base + po.z);
        float4 v3 = *(const float4*)(base + po.w);
        const char* srcb = (const char*)g_Bh16 + (size_t)br*512 + bsg;
        const char* srcl = (const char*)g_Bl16 + (size_t)br*512 + bsg;
        uint32_t dstb = su + MOF_B(0,0) + br*528 + bsg;
        uint32_t dstl = su + MOF_B(1,0) + br*528 + bsg;
        cp16u(dstb, srcb); cp16u(dstb + 16, srcb + 16);
        cp16u(dstl, srcl); cp16u(dstl + 16, srcl + 16);
        cp_commit();
        float s0 = wv.x*v0.x + wv.y*v1.x + wv.z*v2.x + wv.w*v3.x;
        float s1 = wv.x*v0.y + wv.y*v1.y + wv.z*v2.y + wv.w*v3.y;
        float s2 = wv.x*v0.z + wv.y*v1.z + wv.z*v2.z + wv.w*v3.z;
        float s3 = wv.x*v0.w + wv.y*v1.w + wv.z*v2.w + wv.w*v3.w;
        uint32_t h01 = bf16x2(s0, s1), h23 = bf16x2(s2, s3);
        float hf0 = __uint_as_float(h01 << 16), hf1 = __uint_as_float(h01 & 0xffff0000u);
        float hf2 = __uint_as_float(h23 << 16), hf3 = __uint_as_float(h23 & 0xffff0000u);
        uint32_t l01 = bf16x2(s0 - hf0, s1 - hf1), l23 = bf16x2(s2 - hf2, s3 - hf3);
        *(uint2*)(sm + MOF_A(0,0) + gp*80 + gk*2) = make_uint2(h01, h23);
        *(uint2*)(sm + MOF_A(1,0) + gp*80 + gk*2) = make_uint2(l01, l23);
        cp_wait0();
    }
    __syncthreads();

    #pragma unroll 1
    for (int i = 0; i < NCH; ++i) {
        int buf = i & 1;

        // param ring prefetch
        if ((i & 7) == 0 && i >= 8 && i <= 56 && tid < 64) {
            int t = (i >> 3) + 1;
            int slot = t & 1;
            int pidx = ((b*KKT + t)*HWSZ) + hw0 + tid;
            pwp[slot*64 + tid] = g_pw[pidx];
            pop[slot*64 + tid] = g_po[pidx];
        }

        // prefetch chunk i+1: gathers into regs, B via cp.async
        float4 v0, v1, v2, v3;
        int slot = 0;
        if (i < NCH - 1) {
            int sn = i + 1;
            slot = (sn >> 3) & 1;
            int4 po = pop[slot*64 + gp];
            const float* base = xb + (sn & 7)*32 + gk;
            v0 = *(const float4*)(base + po.x);
            v1 = *(const float4*)(base + po.y);
            v2 = *(const float4*)(base + po.z);
            v3 = *(const float4*)(base + po.w);
            const char* srcb = (const char*)g_Bh16 + ((size_t)sn*8192 + br*256)*2 + bsg;
            const char* srcl = (const char*)g_Bl16 + ((size_t)sn*8192 + br*256)*2 + bsg;
            uint32_t dstb = su + MOF_B(0, buf^1) + br*528 + bsg;
            uint32_t dstl = su + MOF_B(1, buf^1) + br*528 + bsg;
            cp16u(dstb, srcb); cp16u(dstb + 16, srcb + 16);
            cp16u(dstl, srcl); cp16u(dstl + 16, srcl + 16);
            cp_commit();
        }

        // MMA over chunk i (2 k16 steps)
        uint32_t baseAh = su + MOF_A(0, buf) + (mh + a_row)*80 + a_cb;
        uint32_t baseAl = su + MOF_A(1, buf) + (mh + a_row)*80 + a_cb;
        uint32_t baseBh = su + MOF_B(0, buf) + b_krow*528 + ns*2 + b_cb;
        uint32_t baseBl = su + MOF_B(1, buf) + b_krow*528 + ns*2 + b_cb;
        #pragma unroll
        for (int ks = 0; ks < 2; ++ks) {
            uint32_t aH[2][4], aL[2][4];
            ldm_x4(aH[0], baseAh + ks*32);
            ldm_x4(aH[1], baseAh + 1280 + ks*32);      // +16 rows * 80B
            ldm_x4(aL[0], baseAl + ks*32);
            ldm_x4(aL[1], baseAl + 1280 + ks*32);
            uint32_t bH[4][2], bL[4][2], t4[4];
            ldm_x4t(t4, baseBh + ks*8448);             // +16 k rows * 528B
            bH[0][0]=t4[0]; bH[0][1]=t4[1]; bH[1][0]=t4[2]; bH[1][1]=t4[3];
            ldm_x4t(t4, baseBh + ks*8448 + 32);        // +16 n cols * 2B
            bH[2][0]=t4[0]; bH[2][1]=t4[1]; bH[3][0]=t4[2]; bH[3][1]=t4[3];
            ldm_x4t(t4, baseBl + ks*8448);
            bL[0][0]=t4[0]; bL[0][1]=t4[1]; bL[1][0]=t4[2]; bL[1][1]=t4[3];
            ldm_x4t(t4, baseBl + ks*8448 + 32);
            bL[2][0]=t4[0]; bL[2][1]=t4[1]; bL[3][0]=t4[2]; bL[3][1]=t4[3];
            #pragma unroll
            for (int mt = 0; mt < 2; ++mt)
                #pragma unroll
                for (int nt = 0; nt < 4; ++nt) {
                    mma_bf16(acc[mt][nt], aH[mt], bH[nt]);
                    mma_bf16(acc[mt][nt], aH[mt], bL[nt]);
                    mma_bf16(acc[mt][nt], aL[mt], bH[nt]);
                }
        }

        // blend + split + store A(i+1), wait for B
        if (i < NCH - 1) {
            float4 wv = pwp[slot*64 + gp];
            float s0 = wv.x*v0.x + wv.y*v1.x + wv.z*v2.x + wv.w*v3.x;
            float s1 = wv.x*v0.y + wv.y*v1.y + wv.z*v2.y + wv.w*v3.y;
            float s2 = wv.x*v0.z + wv.y*v1.z + wv.z*v2.z + wv.w*v3.z;
            float s3 = wv.x*v0.w + wv.y*v1.w + wv.z*v2.w + wv.w*v3.w;
            uint32_t h01 = bf16x2(s0, s1), h23 = bf16x2(s2, s3);
            float hf0 = __uint_as_float(h01 << 16), hf1 = __uint_as_float(h01 & 0xffff0000u);
            float hf2 = __uint_as_float(h23 << 16), hf3 = __uint_as_float(h23 & 0xffff0000u);
            uint32_t l01 = bf16x2(s0 - hf0, s1 - hf1), l23 = bf16x2(s2 - hf2, s3 - hf3);
            *(uint2*)(sm + MOF_A(0, buf^1) + gp*80 + gk*2) = make_uint2(h01, h23);
            *(uint2*)(sm + MOF_A(1, buf^1) + gp*80 + gk*2) = make_uint2(l01, l23);
            cp_wait0();
        }
        __syncthreads();
    }

    // epilogue: acc[mt][nt] lane mapping -> out[b][n][h][w]
    {
        float* op = out + ((size_t)(b*CO))*HWSZ + hw0;
        int r0 = mh + (lane >> 2);
        int c0 = ns + (lane & 3)*2;
        #pragma unroll
        for (int mt = 0; mt < 2; ++mt) {
            int r = r0 + mt*16;
            #pragma unroll
            for (int nt = 0; nt < 4; ++nt) {
                int c = c0 + nt*8;
                op[(size_t)c*HWSZ + r]           = acc[mt][nt][0];
                op[(size_t)(c+1)*HWSZ + r]       = acc[mt][nt][1];
                op[(size_t)c*HWSZ + r + 8]       = acc[mt][nt][2];
                op[(size_t)(c+1)*HWSZ + r + 8]   = acc[mt][nt][3];
            }
        }
    }
}

// ---------------- launch ----------------
extern "C" void kernel_launch(void* const* d_in, const int* in_sizes, int n_in,
                              void* d_out, int out_size) {
    (void)in_sizes; (void)n_in; (void)out_size;
    const float* x  = (const float*)d_in[0];   // (4,256,64,64)
    const float* ow = (const float*)d_in[1];   // (27,256,3,3)
    const float* ob = (const float*)d_in[2];   // (27,)
    const float* dw = (const float*)d_in[3];   // (256,256,3,3)
    float* out = (float*)d_out;                // (4,256,64,64)

    cudaFuncSetAttribute(k_main, cudaFuncAttributeMaxDynamicSharedMemorySize, MSM_TOTAL);

    dim3 tb(32, 8);
    dim3 tg(HWSZ/32, CI/32, BB);
    k_transpose_x<<<tg, tb>>>(x);
    k_prep_b<<<(NCH*8192 + 255)/256, 256>>>(dw);
    k_transpose_wod<<<(KKT*CI*32 + 255)/256, 256>>>(ow);
    k_offset<<<256, 128>>>(ob);
    k_main<<<256, 512, MSM_TOTAL>>>(out);
}

// round 7
// speedup vs baseline: 2.8343x; 1.2978x over previous
#include <cuda_runtime.h>
#include <math.h>
#include <stdint.h>

// Problem constants
#define BB   4
#define CI   256
#define CO   256
#define HH   64
#define WWD  64
#define HWSZ (HH*WWD)
#define KKT  9
#define NCH  72            // K = 2304 in chunks of 32 channels

typedef unsigned long long u64;

// ---------------- scratch (device globals; no allocation) ----------------
__device__ float  g_xt[BB*HWSZ*CI];        // x in NHWC   (16.8 MB)
__device__ unsigned short g_Bh16[NCH*32*256];  // bf16 hi of dcn_w, [chunk][k32][n256]
__device__ unsigned short g_Bl16[NCH*32*256];  // bf16 lo
__device__ unsigned short g_oBh16[NCH*32*32];  // bf16 hi of offset_w, [chunk][k32][n32]
__device__ unsigned short g_oBl16[NCH*32*32];  // bf16 lo
__device__ float4 g_pw[BB*KKT*HWSZ];       // premasked bilinear weights
__device__ int4   g_po[BB*KKT*HWSZ];       // clamped corner element offsets

// ---------------- helpers ----------------
__device__ __forceinline__ void cp16u(uint32_t dst, const void* src) {
    asm volatile("cp.async.cg.shared.global [%0], [%1], 16;\n" :: "r"(dst), "l"(src));
}
__device__ __forceinline__ void cp_commit() {
    asm volatile("cp.async.commit_group;\n" ::);
}
__device__ __forceinline__ void cp_wait0() {
    asm volatile("cp.async.wait_group 0;\n" ::: "memory");
}
__device__ __forceinline__ uint32_t smem_u32(const void* p) {
    uint32_t r;
    asm("{ .reg .u64 t; cvta.to.shared.u64 t, %1; cvt.u32.u64 %0, t; }" : "=r"(r) : "l"(p));
    return r;
}
// pack {lo, hi} floats to bf16x2 (round-to-nearest)
__device__ __forceinline__ uint32_t bf16x2(float lo, float hi) {
    uint32_t r;
    asm("cvt.rn.bf16x2.f32 %0, %1, %2;" : "=r"(r) : "f"(hi), "f"(lo));
    return r;
}
__device__ __forceinline__ void ldm_x4(uint32_t* r, uint32_t addr) {
    asm volatile("ldmatrix.sync.aligned.m8n8.x4.shared.b16 {%0,%1,%2,%3}, [%4];"
        : "=r"(r[0]), "=r"(r[1]), "=r"(r[2]), "=r"(r[3]) : "r"(addr));
}
__device__ __forceinline__ void ldm_x4t(uint32_t* r, uint32_t addr) {
    asm volatile("ldmatrix.sync.aligned.m8n8.x4.trans.shared.b16 {%0,%1,%2,%3}, [%4];"
        : "=r"(r[0]), "=r"(r[1]), "=r"(r[2]), "=r"(r[3]) : "r"(addr));
}
__device__ __forceinline__ void mma_bf16(float* d, const uint32_t* a, const uint32_t* b) {
    asm volatile("mma.sync.aligned.m16n8k16.row.col.f32.bf16.bf16.f32 "
        "{%0,%1,%2,%3}, {%4,%5,%6,%7}, {%8,%9}, {%0,%1,%2,%3};"
        : "+f"(d[0]), "+f"(d[1]), "+f"(d[2]), "+f"(d[3])
        : "r"(a[0]), "r"(a[1]), "r"(a[2]), "r"(a[3]), "r"(b[0]), "r"(b[1]));
}

// ---------------- kernel 1: NCHW -> NHWC transpose of x ----------------
__global__ void k_transpose_x(const float* __restrict__ x) {
    __shared__ float tile[32][33];
    int b  = blockIdx.z;
    int c0 = blockIdx.y * 32;
    int p0 = blockIdx.x * 32;
    int tx = threadIdx.x, ty = threadIdx.y;   // 32 x 8
    #pragma unroll
    for (int j = 0; j < 32; j += 8)
        tile[ty + j][tx] = x[((b*CI + c0 + ty + j)*HWSZ) + p0 + tx];
    __syncthreads();
    #pragma unroll
    for (int j = 0; j < 32; j += 8)
        g_xt[(b*HWSZ + p0 + ty + j)*CI + c0 + tx] = tile[tx][ty + j];
}

// ---------------- kernel 2: dcn_w -> bf16 hi/lo chunk images [chunk][k32][n256] ------
__global__ void k_prep_b(const float* __restrict__ dw) {
    int idx = blockIdx.x * 256 + threadIdx.x;
    if (idx >= NCH*8192) return;
    int kc = idx >> 13;
    int r  = idx & 8191;
    int k  = r >> 8;
    int n  = r & 255;
    int tap = kc >> 3;
    int c   = (kc & 7)*32 + k;
    float v = dw[(n*CI + c)*KKT + tap];
    uint32_t hp = bf16x2(v, 0.0f);
    float hf = __uint_as_float(hp << 16);
    uint32_t lp = bf16x2(v - hf, 0.0f);
    g_Bh16[idx] = (unsigned short)(hp & 0xffff);
    g_Bl16[idx] = (unsigned short)(lp & 0xffff);
}

// ---------------- kernel 2b: offset_w -> bf16 hi/lo chunk images [chunk][k32][n32] ---
__global__ void k_prep_ob(const float* __restrict__ ow) {
    int idx = blockIdx.x * 256 + threadIdx.x;
    if (idx >= NCH*1024) return;
    int kc = idx >> 10;
    int r  = idx & 1023;
    int k  = r >> 5;
    int n  = r & 31;
    int tap = kc >> 3;
    int c   = (kc & 7)*32 + k;
    float v = (n < 27) ? ow[(n*CI + c)*KKT + tap] : 0.0f;
    uint32_t hp = bf16x2(v, 0.0f);
    float hf = __uint_as_float(hp << 16);
    uint32_t lp = bf16x2(v - hf, 0.0f);
    g_oBh16[idx] = (unsigned short)(hp & 0xffff);
    g_oBl16[idx] = (unsigned short)(lp & 0xffff);
}

// ---------------- kernel 3: offset conv via bf16x3 mma.sync + param build ------------
// grid 256 = (b,h). 128 threads (4 warps). M=64 pix, N=32 (27 used), K=2304.
// Warp w: m16 tile = pixels w*16.., all 4 n8 tiles.
// SMEM: A planes [split2][buf2] 64x80B; B planes [split2][buf2] 32x80B; so[64][33].
#define OOF_A(s, f)  (((s)*2 + (f)) * 5120)
#define OOF_B(s, f)  (20480 + ((s)*2 + (f)) * 2560)
#define OOF_SO       30720
#define OSM_TOTAL    39168

__global__ __launch_bounds__(128) void k_offset(const float* __restrict__ ob) {
    __shared__ __align__(16) char sm[OSM_TOTAL];
    uint32_t su = smem_u32(sm);
    float (*so)[33] = (float(*)[33])(sm + OOF_SO);

    int tid  = threadIdx.x;
    int lane = tid & 31;
    int wrp  = tid >> 5;
    int b    = blockIdx.x >> 6;
    int h    = blockIdx.x & 63;

    // warp GEMM mapping
    int g  = lane >> 3, lr = lane & 7;
    int a_row  = (g & 1)*8 + lr;
    int a_cb   = (g >> 1) * 16;
    int b_krow = (g & 1)*8 + lr;
    int b_cb   = (g >> 1) * 16;

    // A-build mapping: 64 pix x 32 ch / 128 thr -> pixel tid>>1, 16 ch each
    int gp = tid >> 1;
    int gk = (tid & 1) * 16;
    // B-load mapping: 2KB per split / 128 thr -> 16B each
    int br = tid >> 2;            // k row 0..31
    int bc = (tid & 3) * 8;       // bf16 col base (8 elems = 16B)

    float acc[4][4];
    #pragma unroll
    for (int j = 0; j < 4; ++j)
        #pragma unroll
        for (int q = 0; q < 4; ++q) acc[j][q] = 0.0f;

    // per-thread tap state (pixel fixed = gp)
    bool valid;
    const float* asrc;
    {
        int y = h - 1, xx = gp - 1;    // tap 0
        valid = (y >= 0) && (xx >= 0) && (xx < WWD);
        asrc = g_xt + (((size_t)(b*HWSZ) + (size_t)(y*WWD + xx)) * CI) + gk;
    }

    // prologue: build chunk 0 into buf 0
    {
        const char* srcb = (const char*)g_oBh16 + (size_t)br*64 + bc*2;
        const char* srcl = (const char*)g_oBl16 + (size_t)br*64 + bc*2;
        cp16u(su + OOF_B(0,0) + br*80 + bc*2, srcb);
        cp16u(su + OOF_B(1,0) + br*80 + bc*2, srcl);
        cp_commit();
        #pragma unroll
        for (int q = 0; q < 4; ++q) {
            float4 f = make_float4(0,0,0,0);
            if (valid) f = *(const float4*)(asrc + q*4);
            uint32_t h01 = bf16x2(f.x, f.y), h23 = bf16x2(f.z, f.w);
            float hf0 = __uint_as_float(h01 << 16), hf1 = __uint_as_float(h01 & 0xffff0000u);
            float hf2 = __uint_as_float(h23 << 16), hf3 = __uint_as_float(h23 & 0xffff0000u);
            uint32_t l01 = bf16x2(f.x - hf0, f.y - hf1), l23 = bf16x2(f.z - hf2, f.w - hf3);
            *(uint2*)(sm + OOF_A(0,0) + gp*80 + (gk + q*4)*2) = make_uint2(h01, h23);
            *(uint2*)(sm + OOF_A(1,0) + gp*80 + (gk + q*4)*2) = make_uint2(l01, l23);
        }
        cp_wait0();
    }
    __syncthreads();

    #pragma unroll 1
    for (int i = 0; i < NCH; ++i) {
        int buf = i & 1;

        // prefetch chunk i+1: x values into regs, B via cp.async
        float4 v[4];
        if (i < NCH - 1) {
            int sn = i + 1;
            if ((sn & 7) == 0) {
                int t = sn >> 3;
                int y = h + t/3 - 1, xx = gp + t%3 - 1;
                valid = (y >= 0) && (y < HH) && (xx >= 0) && (xx < WWD);
                asrc = g_xt + (((size_t)(b*HWSZ) + (size_t)(y*WWD + xx)) * CI) + gk;
            }
            const float* p = asrc + (sn & 7)*32;
            #pragma unroll
            for (int q = 0; q < 4; ++q)
                v[q] = valid ? *(const float4*)(p + q*4) : make_float4(0,0,0,0);
            const char* srcb = (const char*)g_oBh16 + ((size_t)sn*1024 + br*32)*2 + bc*2;
            const char* srcl = (const char*)g_oBl16 + ((size_t)sn*1024 + br*32)*2 + bc*2;
            cp16u(su + OOF_B(0, buf^1) + br*80 + bc*2, srcb);
            cp16u(su + OOF_B(1, buf^1) + br*80 + bc*2, srcl);
            cp_commit();
        }

        // MMA over chunk i (2 k16 steps, 1 m16 x 4 n8, 3 splits)
        uint32_t baseAh = su + OOF_A(0, buf) + (wrp*16 + a_row)*80 + a_cb;
        uint32_t baseAl = su + OOF_A(1, buf) + (wrp*16 + a_row)*80 + a_cb;
        uint32_t baseBh = su + OOF_B(0, buf) + b_krow*80 + b_cb;
        uint32_t baseBl = su + OOF_B(1, buf) + b_krow*80 + b_cb;
        #pragma unroll
        for (int ks = 0; ks < 2; ++ks) {
            uint32_t aH[4], aL[4];
            ldm_x4(aH, baseAh + ks*32);
            ldm_x4(aL, baseAl + ks*32);
            uint32_t bH[4][2], bL[4][2], t4[4];
            ldm_x4t(t4, baseBh + ks*1280);        // +16 k rows * 80B
            bH[0][0]=t4[0]; bH[0][1]=t4[1]; bH[1][0]=t4[2]; bH[1][1]=t4[3];
            ldm_x4t(t4, baseBh + ks*1280 + 32);   // +16 n cols * 2B
            bH[2][0]=t4[0]; bH[2][1]=t4[1]; bH[3][0]=t4[2]; bH[3][1]=t4[3];
            ldm_x4t(t4, baseBl + ks*1280);
            bL[0][0]=t4[0]; bL[0][1]=t4[1]; bL[1][0]=t4[2]; bL[1][1]=t4[3];
            ldm_x4t(t4, baseBl + ks*1280 + 32);
            bL[2][0]=t4[0]; bL[2][1]=t4[1]; bL[3][0]=t4[2]; bL[3][1]=t4[3];
            #pragma unroll
            for (int nt = 0; nt < 4; ++nt) {
                mma_bf16(acc[nt], aH, bH[nt]);
                mma_bf16(acc[nt], aH, bL[nt]);
                mma_bf16(acc[nt], aL, bH[nt]);
            }
        }

        // convert + store A(i+1), wait for B
        if (i < NCH - 1) {
            int nb = buf ^ 1;
            #pragma unroll
            for (int q = 0; q < 4; ++q) {
                uint32_t h01 = bf16x2(v[q].x, v[q].y), h23 = bf16x2(v[q].z, v[q].w);
                float hf0 = __uint_as_float(h01 << 16), hf1 = __uint_as_float(h01 & 0xffff0000u);
                float hf2 = __uint_as_float(h23 << 16), hf3 = __uint_as_float(h23 & 0xffff0000u);
                uint32_t l01 = bf16x2(v[q].x - hf0, v[q].y - hf1);
                uint32_t l23 = bf16x2(v[q].z - hf2, v[q].w - hf3);
                *(uint2*)(sm + OOF_A(0, nb) + gp*80 + (gk + q*4)*2) = make_uint2(h01, h23);
                *(uint2*)(sm + OOF_A(1, nb) + gp*80 + (gk + q*4)*2) = make_uint2(l01, l23);
            }
            cp_wait0();
        }
        __syncthreads();
    }

    // scatter conv result to so[pix][oc]
    {
        int r0 = wrp*16 + (lane >> 2);
        int c0 = (lane & 3)*2;
        #pragma unroll
        for (int nt = 0; nt < 4; ++nt) {
            int c = c0 + nt*8;
            so[r0][c]       = acc[nt][0];
            so[r0][c+1]     = acc[nt][1];
            so[r0 + 8][c]   = acc[nt][2];
            so[r0 + 8][c+1] = acc[nt][3];
        }
    }
    __syncthreads();

    if (tid < 64) {
        float ov[27];
        #pragma unroll
        for (int oc = 0; oc < 27; ++oc) ov[oc] = so[tid][oc] + ob[oc];

        int w  = tid;
        int hw = h * WWD + w;
        #pragma unroll
        for (int kk = 0; kk < 9; ++kk) {
            float dy = ov[2*kk];
            float dx = ov[2*kk + 1];
            float m  = 1.0f / (1.0f + expf(-ov[18 + kk]));
            int ki = kk / 3, kj = kk % 3;
            float py = (float)(h - 1 + ki) + dy;
            float px = (float)(w - 1 + kj) + dx;
            float fy = floorf(py), fx = floorf(px);
            float wy = py - fy,    wx = px - fx;
            int y0 = (int)fy, x0 = (int)fx;
            int y1 = y0 + 1,  x1 = x0 + 1;

            bool vy0 = (y0 >= 0) && (y0 < HH);
            bool vy1 = (y1 >= 0) && (y1 < HH);
            bool vx0 = (x0 >= 0) && (x0 < WWD);
            bool vx1 = (x1 >= 0) && (x1 < WWD);

            float w00 = (1.0f - wy) * (1.0f - wx) * m * ((vy0 && vx0) ? 1.0f : 0.0f);
            float w01 = (1.0f - wy) * wx          * m * ((vy0 && vx1) ? 1.0f : 0.0f);
            float w10 = wy * (1.0f - wx)          * m * ((vy1 && vx0) ? 1.0f : 0.0f);
            float w11 = wy * wx                   * m * ((vy1 && vx1) ? 1.0f : 0.0f);

            int yc0 = min(max(y0, 0), HH - 1);
            int yc1 = min(max(y1, 0), HH - 1);
            int xc0 = min(max(x0, 0), WWD - 1);
            int xc1 = min(max(x1, 0), WWD - 1);

            int idx = ((b*KKT + kk)*HWSZ) + hw;
            g_pw[idx] = make_float4(w00, w01, w10, w11);
            g_po[idx] = make_int4((yc0*WWD + xc0)*CI, (yc0*WWD + xc1)*CI,
                                  (yc1*WWD + xc0)*CI, (yc1*WWD + xc1)*CI);
        }
    }
}

// ---------------- kernel 4: fused bilinear-sample + bf16x3 mma.sync GEMM -------------
// (byte-identical to round-6 winner)
#define MOF_A(s, f)  (((s)*2 + (f)) * 5120)
#define MOF_B(s, f)  (20480 + ((s)*2 + (f)) * 16896)
#define MOF_PW       88064
#define MOF_PO       90112
#define MSM_TOTAL    92160

__global__ __launch_bounds__(512, 1) void k_main(float* __restrict__ out) {
    extern __shared__ char sm[];
    uint32_t su = smem_u32(sm);

    int tid  = threadIdx.x;
    int lane = tid & 31;
    int wid  = tid >> 5;
    int b    = blockIdx.x >> 6;
    int h    = blockIdx.x & 63;
    int hw0  = h * WWD;
    const float* xb = g_xt + (size_t)b * HWSZ * CI;

    int mh = (wid & 1) * 32;
    int ns = (wid >> 1) * 32;
    int g  = lane >> 3, lr = lane & 7;
    int a_row = (g & 1)*8 + lr;
    int a_cb  = (g >> 1) * 16;
    int b_krow = (g & 1)*8 + lr;
    int b_cb  = (g >> 1) * 16;

    int gp = tid >> 3;
    int gk = (tid & 7) * 4;
    int br  = tid >> 4;
    int bsg = (tid & 15) * 32;

    float4* pwp = (float4*)(sm + MOF_PW);
    int4*   pop = (int4*)  (sm + MOF_PO);

    float acc[2][4][4];
    #pragma unroll
    for (int i = 0; i < 2; ++i)
        #pragma unroll
        for (int j = 0; j < 4; ++j)
            #pragma unroll
            for (int q = 0; q < 4; ++q) acc[i][j][q] = 0.0f;

    if (tid < 128) {
        int t = tid >> 6;
        int pp = tid & 63;
        int pidx = ((b*KKT + t)*HWSZ) + hw0 + pp;
        pwp[t*64 + pp] = g_pw[pidx];
        pop[t*64 + pp] = g_po[pidx];
    }
    __syncthreads();

    {
        float4 wv = pwp[gp];
        int4   po = pop[gp];
        const float* base = xb + gk;
        float4 v0 = *(const float4*)(base + po.x);
        float4 v1 = *(const float4*)(base + po.y);
        float4 v2 = *(const float4*)(base + po.z);
        float4 v3 = *(const float4*)(base + po.w);
        const char* srcb = (const char*)g_Bh16 + (size_t)br*512 + bsg;
        const char* srcl = (const char*)g_Bl16 + (size_t)br*512 + bsg;
        uint32_t dstb = su + MOF_B(0,0) + br*528 + bsg;
        uint32_t dstl = su + MOF_B(1,0) + br*528 + bsg;
        cp16u(dstb, srcb); cp16u(dstb + 16, srcb + 16);
        cp16u(dstl, srcl); cp16u(dstl + 16, srcl + 16);
        cp_commit();
        float s0 = wv.x*v0.x + wv.y*v1.x + wv.z*v2.x + wv.w*v3.x;
        float s1 = wv.x*v0.y + wv.y*v1.y + wv.z*v2.y + wv.w*v3.y;
        float s2 = wv.x*v0.z + wv.y*v1.z + wv.z*v2.z + wv.w*v3.z;
        float s3 = wv.x*v0.w + wv.y*v1.w + wv.z*v2.w + wv.w*v3.w;
        uint32_t h01 = bf16x2(s0, s1), h23 = bf16x2(s2, s3);
        float hf0 = __uint_as_float(h01 << 16), hf1 = __uint_as_float(h01 & 0xffff0000u);
        float hf2 = __uint_as_float(h23 << 16), hf3 = __uint_as_float(h23 & 0xffff0000u);
        uint32_t l01 = bf16x2(s0 - hf0, s1 - hf1), l23 = bf16x2(s2 - hf2, s3 - hf3);
        *(uint2*)(sm + MOF_A(0,0) + gp*80 + gk*2) = make_uint2(h01, h23);
        *(uint2*)(sm + MOF_A(1,0) + gp*80 + gk*2) = make_uint2(l01, l23);
        cp_wait0();
    }
    __syncthreads();

    #pragma unroll 1
    for (int i = 0; i < NCH; ++i) {
        int buf = i & 1;

        if ((i & 7) == 0 && i >= 8 && i <= 56 && tid < 64) {
            int t = (i >> 3) + 1;
            int slot = t & 1;
            int pidx = ((b*KKT + t)*HWSZ) + hw0 + tid;
            pwp[slot*64 + tid] = g_pw[pidx];
            pop[slot*64 + tid] = g_po[pidx];
        }

        float4 v0, v1, v2, v3;
        int slot = 0;
        if (i < NCH - 1) {
            int sn = i + 1;
            slot = (sn >> 3) & 1;
            int4 po = pop[slot*64 + gp];
            const float* base = xb + (sn & 7)*32 + gk;
            v0 = *(const float4*)(base + po.x);
            v1 = *(const float4*)(base + po.y);
            v2 = *(const float4*)(base + po.z);
            v3 = *(const float4*)(base + po.w);
            const char* srcb = (const char*)g_Bh16 + ((size_t)sn*8192 + br*256)*2 + bsg;
            const char* srcl = (const char*)g_Bl16 + ((size_t)sn*8192 + br*256)*2 + bsg;
            uint32_t dstb = su + MOF_B(0, buf^1) + br*528 + bsg;
            uint32_t dstl = su + MOF_B(1, buf^1) + br*528 + bsg;
            cp16u(dstb, srcb); cp16u(dstb + 16, srcb + 16);
            cp16u(dstl, srcl); cp16u(dstl + 16, srcl + 16);
            cp_commit();
        }

        uint32_t baseAh = su + MOF_A(0, buf) + (mh + a_row)*80 + a_cb;
        uint32_t baseAl = su + MOF_A(1, buf) + (mh + a_row)*80 + a_cb;
        uint32_t baseBh = su + MOF_B(0, buf) + b_krow*528 + ns*2 + b_cb;
        uint32_t baseBl = su + MOF_B(1, buf) + b_krow*528 + ns*2 + b_cb;
        #pragma unroll
        for (int ks = 0; ks < 2; ++ks) {
            uint32_t aH[2][4], aL[2][4];
            ldm_x4(aH[0], baseAh + ks*32);
            ldm_x4(aH[1], baseAh + 1280 + ks*32);
            ldm_x4(aL[0], baseAl + ks*32);
            ldm_x4(aL[1], baseAl + 1280 + ks*32);
            uint32_t bH[4][2], bL[4][2], t4[4];
            ldm_x4t(t4, baseBh + ks*8448);
            bH[0][0]=t4[0]; bH[0][1]=t4[1]; bH[1][0]=t4[2]; bH[1][1]=t4[3];
            ldm_x4t(t4, baseBh + ks*8448 + 32);
            bH[2][0]=t4[0]; bH[2][1]=t4[1]; bH[3][0]=t4[2]; bH[3][1]=t4[3];
            ldm_x4t(t4, baseBl + ks*8448);
            bL[0][0]=t4[0]; bL[0][1]=t4[1]; bL[1][0]=t4[2]; bL[1][1]=t4[3];
            ldm_x4t(t4, baseBl + ks*8448 + 32);
            bL[2][0]=t4[0]; bL[2][1]=t4[1]; bL[3][0]=t4[2]; bL[3][1]=t4[3];
            #pragma unroll
            for (int mt = 0; mt < 2; ++mt)
                #pragma unroll
                for (int nt = 0; nt < 4; ++nt) {
                    mma_bf16(acc[mt][nt], aH[mt], bH[nt]);
                    mma_bf16(acc[mt][nt], aH[mt], bL[nt]);
                    mma_bf16(acc[mt][nt], aL[mt], bH[nt]);
                }
        }

        if (i < NCH - 1) {
            float4 wv = pwp[slot*64 + gp];
            float s0 = wv.x*v0.x + wv.y*v1.x + wv.z*v2.x + wv.w*v3.x;
            float s1 = wv.x*v0.y + wv.y*v1.y + wv.z*v2.y + wv.w*v3.y;
            float s2 = wv.x*v0.z + wv.y*v1.z + wv.z*v2.z + wv.w*v3.z;
            float s3 = wv.x*v0.w + wv.y*v1.w + wv.z*v2.w + wv.w*v3.w;
            uint32_t h01 = bf16x2(s0, s1), h23 = bf16x2(s2, s3);
            float hf0 = __uint_as_float(h01 << 16), hf1 = __uint_as_float(h01 & 0xffff0000u);
            float hf2 = __uint_as_float(h23 << 16), hf3 = __uint_as_float(h23 & 0xffff0000u);
            uint32_t l01 = bf16x2(s0 - hf0, s1 - hf1), l23 = bf16x2(s2 - hf2, s3 - hf3);
            *(uint2*)(sm + MOF_A(0, buf^1) + gp*80 + gk*2) = make_uint2(h01, h23);
            *(uint2*)(sm + MOF_A(1, buf^1) + gp*80 + gk*2) = make_uint2(l01, l23);
            cp_wait0();
        }
        __syncthreads();
    }

    {
        float* op = out + ((size_t)(b*CO))*HWSZ + hw0;
        int r0 = mh + (lane >> 2);
        int c0 = ns + (lane & 3)*2;
        #pragma unroll
        for (int mt = 0; mt < 2; ++mt) {
            int r = r0 + mt*16;
            #pragma unroll
            for (int nt = 0; nt < 4; ++nt) {
                int c = c0 + nt*8;
                op[(size_t)c*HWSZ + r]           = acc[mt][nt][0];
                op[(size_t)(c+1)*HWSZ + r]       = acc[mt][nt][1];
                op[(size_t)c*HWSZ + r + 8]       = acc[mt][nt][2];
                op[(size_t)(c+1)*HWSZ + r + 8]   = acc[mt][nt][3];
            }
        }
    }
}

// ---------------- launch ----------------
extern "C" void kernel_launch(void* const* d_in, const int* in_sizes, int n_in,
                              void* d_out, int out_size) {
    (void)in_sizes; (void)n_in; (void)out_size;
    const float* x  = (const float*)d_in[0];   // (4,256,64,64)
    const float* ow = (const float*)d_in[1];   // (27,256,3,3)
    const float* ob = (const float*)d_in[2];   // (27,)
    const float* dw = (const float*)d_in[3];   // (256,256,3,3)
    float* out = (float*)d_out;                // (4,256,64,64)

    cudaFuncSetAttribute(k_main, cudaFuncAttributeMaxDynamicSharedMemorySize, MSM_TOTAL);

    dim3 tb(32, 8);
    dim3 tg(HWSZ/32, CI/32, BB);
    k_transpose_x<<<tg, tb>>>(x);
    k_prep_b<<<(NCH*8192 + 255)/256, 256>>>(dw);
    k_prep_ob<<<(NCH*1024 + 255)/256, 256>>>(ow);
    k_offset<<<256, 128>>>(ob);
    k_main<<<256, 512, MSM_TOTAL>>>(out);
}

// round 8
// speedup vs baseline: 2.9974x; 1.0575x over previous
#include <cuda_runtime.h>
#include <math.h>
#include <stdint.h>

// Problem constants
#define BB   4
#define CI   256
#define CO   256
#define HH   64
#define WWD  64
#define HWSZ (HH*WWD)
#define KKT  9
#define NCH  72            // K = 2304 in chunks of 32 channels

// ---------------- scratch (device globals; no allocation) ----------------
__device__ float  g_xt[BB*HWSZ*CI];            // x in NHWC   (16.8 MB)
__device__ unsigned short g_Bh16[NCH*32*256];  // bf16 hi of dcn_w, [chunk][k32][n256]
__device__ unsigned short g_Bl16[NCH*32*256];  // bf16 lo
__device__ unsigned short g_oBh16[NCH*32*32];  // bf16 hi of offset_w, [chunk][k32][n32]
__device__ unsigned short g_oBl16[NCH*32*32];  // bf16 lo

// ---------------- helpers ----------------
__device__ __forceinline__ void cp16u(uint32_t dst, const void* src) {
    asm volatile("cp.async.cg.shared.global [%0], [%1], 16;\n" :: "r"(dst), "l"(src));
}
__device__ __forceinline__ void cp_commit() {
    asm volatile("cp.async.commit_group;\n" ::);
}
__device__ __forceinline__ void cp_wait0() {
    asm volatile("cp.async.wait_group 0;\n" ::: "memory");
}
__device__ __forceinline__ uint32_t smem_u32(const void* p) {
    uint32_t r;
    asm("{ .reg .u64 t; cvta.to.shared.u64 t, %1; cvt.u32.u64 %0, t; }" : "=r"(r) : "l"(p));
    return r;
}
// pack {lo, hi} floats to bf16x2 (round-to-nearest); lo in low 16 bits
__device__ __forceinline__ uint32_t bf16x2(float lo, float hi) {
    uint32_t r;
    asm("cvt.rn.bf16x2.f32 %0, %1, %2;" : "=r"(r) : "f"(hi), "f"(lo));
    return r;
}
__device__ __forceinline__ void ldm_x4(uint32_t* r, uint32_t addr) {
    asm volatile("ldmatrix.sync.aligned.m8n8.x4.shared.b16 {%0,%1,%2,%3}, [%4];"
        : "=r"(r[0]), "=r"(r[1]), "=r"(r[2]), "=r"(r[3]) : "r"(addr));
}
__device__ __forceinline__ void ldm_x4t(uint32_t* r, uint32_t addr) {
    asm volatile("ldmatrix.sync.aligned.m8n8.x4.trans.shared.b16 {%0,%1,%2,%3}, [%4];"
        : "=r"(r[0]), "=r"(r[1]), "=r"(r[2]), "=r"(r[3]) : "r"(addr));
}
__device__ __forceinline__ void mma_bf16(float* d, const uint32_t* a, const uint32_t* b) {
    asm volatile("mma.sync.aligned.m16n8k16.row.col.f32.bf16.bf16.f32 "
        "{%0,%1,%2,%3}, {%4,%5,%6,%7}, {%8,%9}, {%0,%1,%2,%3};"
        : "+f"(d[0]), "+f"(d[1]), "+f"(d[2]), "+f"(d[3])
        : "r"(a[0]), "r"(a[1]), "r"(a[2]), "r"(a[3]), "r"(b[0]), "r"(b[1]));
}
// split float4 -> hi/lo bf16x2 pairs
__device__ __forceinline__ void split4(float4 f, uint2& hh, uint2& ll) {
    uint32_t h01 = bf16x2(f.x, f.y), h23 = bf16x2(f.z, f.w);
    float hf0 = __uint_as_float(h01 << 16), hf1 = __uint_as_float(h01 & 0xffff0000u);
    float hf2 = __uint_as_float(h23 << 16), hf3 = __uint_as_float(h23 & 0xffff0000u);
    uint32_t l01 = bf16x2(f.x - hf0, f.y - hf1), l23 = bf16x2(f.z - hf2, f.w - hf3);
    hh = make_uint2(h01, h23);
    ll = make_uint2(l01, l23);
}

// ---------------- kernel 1: NCHW -> NHWC transpose of x ----------------
__global__ void k_transpose_x(const float* __restrict__ x) {
    __shared__ float tile[32][33];
    int b  = blockIdx.z;
    int c0 = blockIdx.y * 32;
    int p0 = blockIdx.x * 32;
    int tx = threadIdx.x, ty = threadIdx.y;   // 32 x 8
    #pragma unroll
    for (int j = 0; j < 32; j += 8)
        tile[ty + j][tx] = x[((b*CI + c0 + ty + j)*HWSZ) + p0 + tx];
    __syncthreads();
    #pragma unroll
    for (int j = 0; j < 32; j += 8)
        g_xt[(b*HWSZ + p0 + ty + j)*CI + c0 + tx] = tile[tx][ty + j];
}

// ---------------- kernel 2: dcn_w -> bf16 hi/lo chunk images [chunk][k32][n256] ------
__global__ void k_prep_b(const float* __restrict__ dw) {
    int idx = blockIdx.x * 256 + threadIdx.x;
    if (idx >= NCH*8192) return;
    int kc = idx >> 13;
    int r  = idx & 8191;
    int k  = r >> 8;
    int n  = r & 255;
    int tap = kc >> 3;
    int c   = (kc & 7)*32 + k;
    float v = dw[(n*CI + c)*KKT + tap];
    uint32_t hp = bf16x2(v, 0.0f);
    float hf = __uint_as_float(hp << 16);
    uint32_t lp = bf16x2(v - hf, 0.0f);
    g_Bh16[idx] = (unsigned short)(hp & 0xffff);
    g_Bl16[idx] = (unsigned short)(lp & 0xffff);
}

// ---------------- kernel 2b: offset_w -> bf16 hi/lo chunk images [chunk][k32][n32] ---
__global__ void k_prep_ob(const float* __restrict__ ow) {
    int idx = blockIdx.x * 256 + threadIdx.x;
    if (idx >= NCH*1024) return;
    int kc = idx >> 10;
    int r  = idx & 1023;
    int k  = r >> 5;
    int n  = r & 31;
    int tap = kc >> 3;
    int c   = (kc & 7)*32 + k;
    float v = (n < 27) ? ow[(n*CI + c)*KKT + tap] : 0.0f;
    uint32_t hp = bf16x2(v, 0.0f);
    float hf = __uint_as_float(hp << 16);
    uint32_t lp = bf16x2(v - hf, 0.0f);
    g_oBh16[idx] = (unsigned short)(hp & 0xffff);
    g_oBl16[idx] = (unsigned short)(lp & 0xffff);
}

// ---------------- fused kernel: offset conv + param build + sample + main GEMM -------
// grid 256 = (b,h), 512 threads (16 warps).
// SMEM byte offsets:
#define FA(s, f)   (((s)*2 + (f)) * 5120)                 // A planes 64 x 80B
#define FB(s, f)   (20480 + ((s)*2 + (f)) * 16896)        // main B planes 32 x 528B
#define FBC(s, f)  (88064 + ((s)*2 + (f)) * 2560)         // conv B planes 32 x 80B
#define FPW        98304                                  // float4[9][64]
#define FPO        107520                                 // int4[9][64]
#define FSO        116736                                 // float[64][33]
#define FSM_TOTAL  125184

__global__ __launch_bounds__(512, 1) void k_fused(float* __restrict__ out,
                                                  const float* __restrict__ ob) {
    extern __shared__ char sm[];
    uint32_t su = smem_u32(sm);

    int tid  = threadIdx.x;
    int lane = tid & 31;
    int wid  = tid >> 5;
    int b    = blockIdx.x >> 6;
    int h    = blockIdx.x & 63;
    int hw0  = h * WWD;
    const float* xb = g_xt + (size_t)b * HWSZ * CI;

    // common ldmatrix lane mapping
    int g  = lane >> 3, lr = lane & 7;
    int a_row = (g & 1)*8 + lr;
    int a_cb  = (g >> 1) * 16;
    int b_krow = (g & 1)*8 + lr;
    int b_cb  = (g >> 1) * 16;

    // A-build mapping: 64 pix x 32 ch / 512 thr -> 4 ch per thread
    int gp = tid >> 3;
    int gk = (tid & 7) * 4;

    float4* spw = (float4*)(sm + FPW);
    int4*   spo = (int4*)  (sm + FPO);
    float (*so)[33] = (float(*)[33])(sm + FSO);

    // ======================= PHASE 1: offset conv (N=32) =======================
    {
        // conv warp tiles: warps 0..7 -> mt = wid&3 (m16), npair = wid>>2 (n16)
        int mt = wid & 3;
        int npair = (wid >> 2) & 1;
        bool mma_act = (wid < 8);

        // conv B-load mapping: tid<128 -> k row tid>>2, 16B segment (tid&3)
        int cbr = (tid & 127) >> 2;
        int cbs = (tid & 3) * 16;
        bool bld = (tid < 128);

        float accc[2][4];
        #pragma unroll
        for (int j = 0; j < 2; ++j)
            #pragma unroll
            for (int q = 0; q < 4; ++q) accc[j][q] = 0.0f;

        // per-thread tap state
        bool valid;
        const float* asrc;
        {
            int y = h - 1, xx = gp - 1;   // tap 0
            valid = (y >= 0) && (y < HH) && (xx >= 0) && (xx < WWD);
            asrc = g_xt + (((size_t)(b*HWSZ) + (size_t)(y*WWD + xx)) * CI) + gk;
        }

        // prologue chunk 0
        {
            if (bld) {
                cp16u(su + FBC(0,0) + cbr*80 + cbs, (const char*)g_oBh16 + (size_t)cbr*64 + cbs);
                cp16u(su + FBC(1,0) + cbr*80 + cbs, (const char*)g_oBl16 + (size_t)cbr*64 + cbs);
            }
            cp_commit();
            float4 f = valid ? *(const float4*)asrc : make_float4(0,0,0,0);
            uint2 hh, ll;
            split4(f, hh, ll);
            *(uint2*)(sm + FA(0,0) + gp*80 + gk*2) = hh;
            *(uint2*)(sm + FA(1,0) + gp*80 + gk*2) = ll;
            cp_wait0();
        }
        __syncthreads();

        #pragma unroll 1
        for (int i = 0; i < NCH; ++i) {
            int buf = i & 1;

            float4 v = make_float4(0,0,0,0);
            if (i < NCH - 1) {
                int sn = i + 1;
                if ((sn & 7) == 0) {
                    int t = sn >> 3;
                    int y = h + t/3 - 1, xx = gp + t%3 - 1;
                    valid = (y >= 0) && (y < HH) && (xx >= 0) && (xx < WWD);
                    asrc = g_xt + (((size_t)(b*HWSZ) + (size_t)(y*WWD + xx)) * CI) + gk;
                }
                if (valid) v = *(const float4*)(asrc + (sn & 7)*32);
                if (bld) {
                    const char* sbh = (const char*)g_oBh16 + ((size_t)sn*1024 + cbr*32)*2 + cbs;
                    const char* sbl = (const char*)g_oBl16 + ((size_t)sn*1024 + cbr*32)*2 + cbs;
                    cp16u(su + FBC(0, buf^1) + cbr*80 + cbs, sbh);
                    cp16u(su + FBC(1, buf^1) + cbr*80 + cbs, sbl);
                }
                cp_commit();
            }

            if (mma_act) {
                uint32_t baseAh = su + FA(0, buf) + (mt*16 + a_row)*80 + a_cb;
                uint32_t baseAl = su + FA(1, buf) + (mt*16 + a_row)*80 + a_cb;
                uint32_t baseBh = su + FBC(0, buf) + b_krow*80 + npair*32 + b_cb;
                uint32_t baseBl = su + FBC(1, buf) + b_krow*80 + npair*32 + b_cb;
                #pragma unroll
                for (int ks = 0; ks < 2; ++ks) {
                    uint32_t aH[4], aL[4];
                    ldm_x4(aH, baseAh + ks*32);
                    ldm_x4(aL, baseAl + ks*32);
                    uint32_t bH[2][2], bL[2][2], t4[4];
                    ldm_x4t(t4, baseBh + ks*1280);
                    bH[0][0]=t4[0]; bH[0][1]=t4[1]; bH[1][0]=t4[2]; bH[1][1]=t4[3];
                    ldm_x4t(t4, baseBl + ks*1280);
                    bL[0][0]=t4[0]; bL[0][1]=t4[1]; bL[1][0]=t4[2]; bL[1][1]=t4[3];
                    #pragma unroll
                    for (int nt = 0; nt < 2; ++nt) {
                        mma_bf16(accc[nt], aH, bH[nt]);
                        mma_bf16(accc[nt], aH, bL[nt]);
                        mma_bf16(accc[nt], aL, bH[nt]);
                    }
                }
            }

            if (i < NCH - 1) {
                uint2 hh, ll;
                split4(v, hh, ll);
                *(uint2*)(sm + FA(0, buf^1) + gp*80 + gk*2) = hh;
                *(uint2*)(sm + FA(1, buf^1) + gp*80 + gk*2) = ll;
                cp_wait0();
            }
            __syncthreads();
        }

        // scatter conv result
        if (mma_act) {
            int r0 = mt*16 + (lane >> 2);
            int c0 = npair*16 + (lane & 3)*2;
            #pragma unroll
            for (int nt = 0; nt < 2; ++nt) {
                int c = c0 + nt*8;
                so[r0][c]       = accc[nt][0];
                so[r0][c+1]     = accc[nt][1];
                so[r0 + 8][c]   = accc[nt][2];
                so[r0 + 8][c+1] = accc[nt][3];
            }
        }
        __syncthreads();
    }

    // ======================= PHASE 2: param build =======================
    if (tid < 64) {
        float ov[27];
        #pragma unroll
        for (int oc = 0; oc < 27; ++oc) ov[oc] = so[tid][oc] + ob[oc];

        int w = tid;
        #pragma unroll
        for (int kk = 0; kk < 9; ++kk) {
            float dy = ov[2*kk];
            float dx = ov[2*kk + 1];
            float m  = 1.0f / (1.0f + expf(-ov[18 + kk]));
            int ki = kk / 3, kj = kk % 3;
            float py = (float)(h - 1 + ki) + dy;
            float px = (float)(w - 1 + kj) + dx;
            float fy = floorf(py), fx = floorf(px);
            float wy = py - fy,    wx = px - fx;
            int y0 = (int)fy, x0 = (int)fx;
            int y1 = y0 + 1,  x1 = x0 + 1;

            bool vy0 = (y0 >= 0) && (y0 < HH);
            bool vy1 = (y1 >= 0) && (y1 < HH);
            bool vx0 = (x0 >= 0) && (x0 < WWD);
            bool vx1 = (x1 >= 0) && (x1 < WWD);

            float w00 = (1.0f - wy) * (1.0f - wx) * m * ((vy0 && vx0) ? 1.0f : 0.0f);
            float w01 = (1.0f - wy) * wx          * m * ((vy0 && vx1) ? 1.0f : 0.0f);
            float w10 = wy * (1.0f - wx)          * m * ((vy1 && vx0) ? 1.0f : 0.0f);
            float w11 = wy * wx                   * m * ((vy1 && vx1) ? 1.0f : 0.0f);

            int yc0 = min(max(y0, 0), HH - 1);
            int yc1 = min(max(y1, 0), HH - 1);
            int xc0 = min(max(x0, 0), WWD - 1);
            int xc1 = min(max(x1, 0), WWD - 1);

            spw[kk*64 + w] = make_float4(w00, w01, w10, w11);
            spo[kk*64 + w] = make_int4((yc0*WWD + xc0)*CI, (yc0*WWD + xc1)*CI,
                                       (yc1*WWD + xc0)*CI, (yc1*WWD + xc1)*CI);
        }
    }
    __syncthreads();

    // ======================= PHASE 3: main GEMM =======================
    {
        int mh = (wid & 1) * 32;
        int ns = (wid >> 1) * 32;
        int br  = tid >> 4;
        int bsg = (tid & 15) * 32;

        float acc[2][4][4];
        #pragma unroll
        for (int i = 0; i < 2; ++i)
            #pragma unroll
            for (int j = 0; j < 4; ++j)
                #pragma unroll
                for (int q = 0; q < 4; ++q) acc[i][j][q] = 0.0f;

        // prologue chunk 0
        {
            float4 wv = spw[gp];
            int4   po = spo[gp];
            const float* base = xb + gk;
            float4 v0 = *(const float4*)(base + po.x);
            float4 v1 = *(const float4*)(base + po.y);
            float4 v2 = *(const float4*)(base + po.z);
            float4 v3 = *(const float4*)(base + po.w);
            const char* srcb = (const char*)g_Bh16 + (size_t)br*512 + bsg;
            const char* srcl = (const char*)g_Bl16 + (size_t)br*512 + bsg;
            uint32_t dstb = su + FB(0,0) + br*528 + bsg;
            uint32_t dstl = su + FB(1,0) + br*528 + bsg;
            cp16u(dstb, srcb); cp16u(dstb + 16, srcb + 16);
            cp16u(dstl, srcl); cp16u(dstl + 16, srcl + 16);
            cp_commit();
            float4 s;
            s.x = wv.x*v0.x + wv.y*v1.x + wv.z*v2.x + wv.w*v3.x;
            s.y = wv.x*v0.y + wv.y*v1.y + wv.z*v2.y + wv.w*v3.y;
            s.z = wv.x*v0.z + wv.y*v1.z + wv.z*v2.z + wv.w*v3.z;
            s.w = wv.x*v0.w + wv.y*v1.w + wv.z*v2.w + wv.w*v3.w;
            uint2 hh, ll;
            split4(s, hh, ll);
            *(uint2*)(sm + FA(0,0) + gp*80 + gk*2) = hh;
            *(uint2*)(sm + FA(1,0) + gp*80 + gk*2) = ll;
            cp_wait0();
        }
        __syncthreads();

        #pragma unroll 1
        for (int i = 0; i < NCH; ++i) {
            int buf = i & 1;

            float4 v0, v1, v2, v3;
            float4 wv;
            if (i < NCH - 1) {
                int sn = i + 1;
                int t = sn >> 3;
                int4 po = spo[t*64 + gp];
                wv = spw[t*64 + gp];
                const float* base = xb + (sn & 7)*32 + gk;
                v0 = *(const float4*)(base + po.x);
                v1 = *(const float4*)(base + po.y);
                v2 = *(const float4*)(base + po.z);
                v3 = *(const float4*)(base + po.w);
                const char* srcb = (const char*)g_Bh16 + ((size_t)sn*8192 + br*256)*2 + bsg;
                const char* srcl = (const char*)g_Bl16 + ((size_t)sn*8192 + br*256)*2 + bsg;
                uint32_t dstb = su + FB(0, buf^1) + br*528 + bsg;
                uint32_t dstl = su + FB(1, buf^1) + br*528 + bsg;
                cp16u(dstb, srcb); cp16u(dstb + 16, srcb + 16);
                cp16u(dstl, srcl); cp16u(dstl + 16, srcl + 16);
                cp_commit();
            }

            uint32_t baseAh = su + FA(0, buf) + (mh + a_row)*80 + a_cb;
            uint32_t baseAl = su + FA(1, buf) + (mh + a_row)*80 + a_cb;
            uint32_t baseBh = su + FB(0, buf) + b_krow*528 + ns*2 + b_cb;
            uint32_t baseBl = su + FB(1, buf) + b_krow*528 + ns*2 + b_cb;
            #pragma unroll
            for (int ks = 0; ks < 2; ++ks) {
                uint32_t aH[2][4], aL[2][4];
                ldm_x4(aH[0], baseAh + ks*32);
                ldm_x4(aH[1], baseAh + 1280 + ks*32);
                ldm_x4(aL[0], baseAl + ks*32);
                ldm_x4(aL[1], baseAl + 1280 + ks*32);
                uint32_t bH[4][2], bL[4][2], t4[4];
                ldm_x4t(t4, baseBh + ks*8448);
                bH[0][0]=t4[0]; bH[0][1]=t4[1]; bH[1][0]=t4[2]; bH[1][1]=t4[3];
                ldm_x4t(t4, baseBh + ks*8448 + 32);
                bH[2][0]=t4[0]; bH[2][1]=t4[1]; bH[3][0]=t4[2]; bH[3][1]=t4[3];
                ldm_x4t(t4, baseBl + ks*8448);
                bL[0][0]=t4[0]; bL[0][1]=t4[1]; bL[1][0]=t4[2]; bL[1][1]=t4[3];
                ldm_x4t(t4, baseBl + ks*8448 + 32);
                bL[2][0]=t4[0]; bL[2][1]=t4[1]; bL[3][0]=t4[2]; bL[3][1]=t4[3];
                #pragma unroll
                for (int mt = 0; mt < 2; ++mt)
                    #pragma unroll
                    for (int nt = 0; nt < 4; ++nt) {
                        mma_bf16(acc[mt][nt], aH[mt], bH[nt]);
                        mma_bf16(acc[mt][nt], aH[mt], bL[nt]);
                        mma_bf16(acc[mt][nt], aL[mt], bH[nt]);
                    }
            }

            if (i < NCH - 1) {
                float4 s;
                s.x = wv.x*v0.x + wv.y*v1.x + wv.z*v2.x + wv.w*v3.x;
                s.y = wv.x*v0.y + wv.y*v1.y + wv.z*v2.y + wv.w*v3.y;
                s.z = wv.x*v0.z + wv.y*v1.z + wv.z*v2.z + wv.w*v3.z;
                s.w = wv.x*v0.w + wv.y*v1.w + wv.z*v2.w + wv.w*v3.w;
                uint2 hh, ll;
                split4(s, hh, ll);
                *(uint2*)(sm + FA(0, buf^1) + gp*80 + gk*2) = hh;
                *(uint2*)(sm + FA(1, buf^1) + gp*80 + gk*2) = ll;
                cp_wait0();
            }
            __syncthreads();
        }

        // epilogue
        {
            float* op = out + ((size_t)(b*CO))*HWSZ + hw0;
            int r0 = mh + (lane >> 2);
            int c0 = ns + (lane & 3)*2;
            #pragma unroll
            for (int mt = 0; mt < 2; ++mt) {
                int r = r0 + mt*16;
                #pragma unroll
                for (int nt = 0; nt < 4; ++nt) {
                    int c = c0 + nt*8;
                    op[(size_t)c*HWSZ + r]           = acc[mt][nt][0];
                    op[(size_t)(c+1)*HWSZ + r]       = acc[mt][nt][1];
                    op[(size_t)c*HWSZ + r + 8]       = acc[mt][nt][2];
                    op[(size_t)(c+1)*HWSZ + r + 8]   = acc[mt][nt][3];
                }
            }
        }
    }
}

// ---------------- launch ----------------
extern "C" void kernel_launch(void* const* d_in, const int* in_sizes, int n_in,
                              void* d_out, int out_size) {
    (void)in_sizes; (void)n_in; (void)out_size;
    const float* x  = (const float*)d_in[0];   // (4,256,64,64)
    const float* ow = (const float*)d_in[1];   // (27,256,3,3)
    const float* ob = (const float*)d_in[2];   // (27,)
    const float* dw = (const float*)d_in[3];   // (256,256,3,3)
    float* out = (float*)d_out;                // (4,256,64,64)

    cudaFuncSetAttribute(k_fused, cudaFuncAttributeMaxDynamicSharedMemorySize, FSM_TOTAL);

    dim3 tb(32, 8);
    dim3 tg(HWSZ/32, CI/32, BB);
    k_transpose_x<<<tg, tb>>>(x);
    k_prep_b<<<(NCH*8192 + 255)/256, 256>>>(dw);
    k_prep_ob<<<(NCH*1024 + 255)/256, 256>>>(ow);
    k_fused<<<256, 512, FSM_TOTAL>>>(out, ob);
}

// round 9
// speedup vs baseline: 3.0076x; 1.0034x over previous
#include <cuda_runtime.h>
#include <math.h>
#include <stdint.h>

// Problem constants
#define BB   4
#define CI   256
#define CO   256
#define HH   64
#define WWD  64
#define HWSZ (HH*WWD)
#define KKT  9
#define NCH  72            // K = 2304 in chunks of 32 channels

// ---------------- scratch (device globals; no allocation) ----------------
__device__ float  g_xt[BB*HWSZ*CI];            // x in NHWC   (16.8 MB)
__device__ unsigned short g_Bh16[NCH*32*256];  // bf16 hi of dcn_w, [chunk][k32][n256]
__device__ unsigned short g_Bl16[NCH*32*256];  // bf16 lo
__device__ unsigned short g_oBh16[NCH*32*32];  // bf16 hi of offset_w, [chunk][k32][n32]
__device__ unsigned short g_oBl16[NCH*32*32];  // bf16 lo

// ---------------- helpers ----------------
__device__ __forceinline__ void cp16u(uint32_t dst, const void* src) {
    asm volatile("cp.async.cg.shared.global [%0], [%1], 16;\n" :: "r"(dst), "l"(src));
}
__device__ __forceinline__ void cp_commit() {
    asm volatile("cp.async.commit_group;\n" ::);
}
__device__ __forceinline__ void cp_wait0() {
    asm volatile("cp.async.wait_group 0;\n" ::: "memory");
}
__device__ __forceinline__ uint32_t smem_u32(const void* p) {
    uint32_t r;
    asm("{ .reg .u64 t; cvta.to.shared.u64 t, %1; cvt.u32.u64 %0, t; }" : "=r"(r) : "l"(p));
    return r;
}
// pack {lo, hi} floats to bf16x2 (round-to-nearest); lo in low 16 bits
__device__ __forceinline__ uint32_t bf16x2(float lo, float hi) {
    uint32_t r;
    asm("cvt.rn.bf16x2.f32 %0, %1, %2;" : "=r"(r) : "f"(hi), "f"(lo));
    return r;
}
__device__ __forceinline__ void ldm_x4(uint32_t* r, uint32_t addr) {
    asm volatile("ldmatrix.sync.aligned.m8n8.x4.shared.b16 {%0,%1,%2,%3}, [%4];"
        : "=r"(r[0]), "=r"(r[1]), "=r"(r[2]), "=r"(r[3]) : "r"(addr));
}
__device__ __forceinline__ void ldm_x4t(uint32_t* r, uint32_t addr) {
    asm volatile("ldmatrix.sync.aligned.m8n8.x4.trans.shared.b16 {%0,%1,%2,%3}, [%4];"
        : "=r"(r[0]), "=r"(r[1]), "=r"(r[2]), "=r"(r[3]) : "r"(addr));
}
__device__ __forceinline__ void mma_bf16(float* d, const uint32_t* a, const uint32_t* b) {
    asm volatile("mma.sync.aligned.m16n8k16.row.col.f32.bf16.bf16.f32 "
        "{%0,%1,%2,%3}, {%4,%5,%6,%7}, {%8,%9}, {%0,%1,%2,%3};"
        : "+f"(d[0]), "+f"(d[1]), "+f"(d[2]), "+f"(d[3])
        : "r"(a[0]), "r"(a[1]), "r"(a[2]), "r"(a[3]), "r"(b[0]), "r"(b[1]));
}
// split float4 -> hi/lo bf16x2 pairs
__device__ __forceinline__ void split4(float4 f, uint2& hh, uint2& ll) {
    uint32_t h01 = bf16x2(f.x, f.y), h23 = bf16x2(f.z, f.w);
    float hf0 = __uint_as_float(h01 << 16), hf1 = __uint_as_float(h01 & 0xffff0000u);
    float hf2 = __uint_as_float(h23 << 16), hf3 = __uint_as_float(h23 & 0xffff0000u);
    uint32_t l01 = bf16x2(f.x - hf0, f.y - hf1), l23 = bf16x2(f.z - hf2, f.w - hf3);
    hh = make_uint2(h01, h23);
    ll = make_uint2(l01, l23);
}

// ---------------- kernel 1: NCHW -> NHWC transpose of x ----------------
__global__ void k_transpose_x(const float* __restrict__ x) {
    __shared__ float tile[32][33];
    int b  = blockIdx.z;
    int c0 = blockIdx.y * 32;
    int p0 = blockIdx.x * 32;
    int tx = threadIdx.x, ty = threadIdx.y;   // 32 x 8
    #pragma unroll
    for (int j = 0; j < 32; j += 8)
        tile[ty + j][tx] = x[((b*CI + c0 + ty + j)*HWSZ) + p0 + tx];
    __syncthreads();
    #pragma unroll
    for (int j = 0; j < 32; j += 8)
        g_xt[(b*HWSZ + p0 + ty + j)*CI + c0 + tx] = tile[tx][ty + j];
}

// ---------------- kernel 2: dcn_w -> bf16 hi/lo chunk images [chunk][k32][n256] ------
__global__ void k_prep_b(const float* __restrict__ dw) {
    int idx = blockIdx.x * 256 + threadIdx.x;
    if (idx >= NCH*8192) return;
    int kc = idx >> 13;
    int r  = idx & 8191;
    int k  = r >> 8;
    int n  = r & 255;
    int tap = kc >> 3;
    int c   = (kc & 7)*32 + k;
    float v = dw[(n*CI + c)*KKT + tap];
    uint32_t hp = bf16x2(v, 0.0f);
    float hf = __uint_as_float(hp << 16);
    uint32_t lp = bf16x2(v - hf, 0.0f);
    g_Bh16[idx] = (unsigned short)(hp & 0xffff);
    g_Bl16[idx] = (unsigned short)(lp & 0xffff);
}

// ---------------- kernel 2b: offset_w -> bf16 hi/lo chunk images [chunk][k32][n32] ---
__global__ void k_prep_ob(const float* __restrict__ ow) {
    int idx = blockIdx.x * 256 + threadIdx.x;
    if (idx >= NCH*1024) return;
    int kc = idx >> 10;
    int r  = idx & 1023;
    int k  = r >> 5;
    int n  = r & 31;
    int tap = kc >> 3;
    int c   = (kc & 7)*32 + k;
    float v = (n < 27) ? ow[(n*CI + c)*KKT + tap] : 0.0f;
    uint32_t hp = bf16x2(v, 0.0f);
    float hf = __uint_as_float(hp << 16);
    uint32_t lp = bf16x2(v - hf, 0.0f);
    g_oBh16[idx] = (unsigned short)(hp & 0xffff);
    g_oBl16[idx] = (unsigned short)(lp & 0xffff);
}

// ---------------- fused kernel: M=128 pixels per block, grid 128 ---------------------
// SMEM byte offsets:
#define FA(s, f)   (((s)*2 + (f)) * 5120)                 // main A planes 64 x 80B
#define FB(s, f)   (20480 + ((s)*2 + (f)) * 16896)        // main B planes 32 x 528B
#define CA(s, f)   (20480 + ((s)*2 + (f)) * 10240)        // conv A planes 128 x 80B (overlays FB)
#define FBC(s, f)  (88064 + ((s)*2 + (f)) * 2560)         // conv B planes 32 x 80B
#define FPW        98304                                  // float4[9][128]
#define FPO        116736                                 // int4[9][128]
#define FSO        135168                                 // float[128][33]
#define FSM_TOTAL  152064

__global__ __launch_bounds__(512, 1) void k_fused(float* __restrict__ out,
                                                  const float* __restrict__ ob) {
    extern __shared__ char sm[];
    uint32_t su = smem_u32(sm);

    int tid  = threadIdx.x;
    int lane = tid & 31;
    int wid  = tid >> 5;
    int b    = blockIdx.x >> 5;
    int hp   = blockIdx.x & 31;          // row pair: rows 2hp, 2hp+1
    int hw0  = hp * 128;
    const float* xb = g_xt + (size_t)b * HWSZ * CI;

    // common ldmatrix lane mapping
    int g  = lane >> 3, lr = lane & 7;
    int a_row = (g & 1)*8 + lr;
    int a_cb  = (g >> 1) * 16;
    int b_krow = (g & 1)*8 + lr;
    int b_cb  = (g >> 1) * 16;

    float4* spw = (float4*)(sm + FPW);
    int4*   spo = (int4*)  (sm + FPO);
    float (*so)[33] = (float(*)[33])(sm + FSO);

    // ======================= PHASE 1: offset conv (M=128, N=32) ====================
    {
        // warp tiles: 8 m16 tiles x 2 n16 pairs, all 16 warps
        int mt = wid & 7;
        int npair = wid >> 3;

        // A-build: 128 pix x 32 ch / 512 thr -> pixel tid>>2, 8 ch each
        int cgp = tid >> 2;
        int cgk = (tid & 3) * 8;
        int prow = cgp >> 6;          // 0/1 within row pair
        int pcol = cgp & 63;

        // conv B-load mapping: tid<128
        int cbr = (tid & 127) >> 2;
        int cbs = (tid & 3) * 16;
        bool bld = (tid < 128);

        float accc[2][4];
        #pragma unroll
        for (int j = 0; j < 2; ++j)
            #pragma unroll
            for (int q = 0; q < 4; ++q) accc[j][q] = 0.0f;

        // per-thread tap state
        bool valid;
        const float* asrc;
        {
            int y = 2*hp + prow - 1, xx = pcol - 1;   // tap 0
            valid = (y >= 0) && (y < HH) && (xx >= 0) && (xx < WWD);
            asrc = g_xt + (((size_t)(b*HWSZ) + (size_t)(y*WWD + xx)) * CI) + cgk;
        }

        // prologue chunk 0
        {
            if (bld) {
                cp16u(su + FBC(0,0) + cbr*80 + cbs, (const char*)g_oBh16 + (size_t)cbr*64 + cbs);
                cp16u(su + FBC(1,0) + cbr*80 + cbs, (const char*)g_oBl16 + (size_t)cbr*64 + cbs);
            }
            cp_commit();
            #pragma unroll
            for (int q = 0; q < 2; ++q) {
                float4 f = valid ? *(const float4*)(asrc + q*4) : make_float4(0,0,0,0);
                uint2 hh, ll;
                split4(f, hh, ll);
                *(uint2*)(sm + CA(0,0) + cgp*80 + (cgk + q*4)*2) = hh;
                *(uint2*)(sm + CA(1,0) + cgp*80 + (cgk + q*4)*2) = ll;
            }
            cp_wait0();
        }
        __syncthreads();

        #pragma unroll 1
        for (int i = 0; i < NCH; ++i) {
            int buf = i & 1;

            float4 v[2];
            v[0] = make_float4(0,0,0,0); v[1] = v[0];
            if (i < NCH - 1) {
                int sn = i + 1;
                if ((sn & 7) == 0) {
                    int t = sn >> 3;
                    int y = 2*hp + prow + t/3 - 1, xx = pcol + t%3 - 1;
                    valid = (y >= 0) && (y < HH) && (xx >= 0) && (xx < WWD);
                    asrc = g_xt + (((size_t)(b*HWSZ) + (size_t)(y*WWD + xx)) * CI) + cgk;
                }
                if (valid) {
                    const float* p = asrc + (sn & 7)*32;
                    v[0] = *(const float4*)p;
                    v[1] = *(const float4*)(p + 4);
                }
                if (bld) {
                    const char* sbh = (const char*)g_oBh16 + ((size_t)sn*1024 + cbr*32)*2 + cbs;
                    const char* sbl = (const char*)g_oBl16 + ((size_t)sn*1024 + cbr*32)*2 + cbs;
                    cp16u(su + FBC(0, buf^1) + cbr*80 + cbs, sbh);
                    cp16u(su + FBC(1, buf^1) + cbr*80 + cbs, sbl);
                }
                cp_commit();
            }

            // conv MMA (2 k16 steps, 1 m16 x 2 n8, 3 splits)
            {
                uint32_t baseAh = su + CA(0, buf) + (mt*16 + a_row)*80 + a_cb;
                uint32_t baseAl = su + CA(1, buf) + (mt*16 + a_row)*80 + a_cb;
                uint32_t baseBh = su + FBC(0, buf) + b_krow*80 + npair*32 + b_cb;
                uint32_t baseBl = su + FBC(1, buf) + b_krow*80 + npair*32 + b_cb;
                #pragma unroll
                for (int ks = 0; ks < 2; ++ks) {
                    uint32_t aH[4], aL[4];
                    ldm_x4(aH, baseAh + ks*32);
                    ldm_x4(aL, baseAl + ks*32);
                    uint32_t bH[2][2], bL[2][2], t4[4];
                    ldm_x4t(t4, baseBh + ks*1280);
                    bH[0][0]=t4[0]; bH[0][1]=t4[1]; bH[1][0]=t4[2]; bH[1][1]=t4[3];
                    ldm_x4t(t4, baseBl + ks*1280);
                    bL[0][0]=t4[0]; bL[0][1]=t4[1]; bL[1][0]=t4[2]; bL[1][1]=t4[3];
                    #pragma unroll
                    for (int nt = 0; nt < 2; ++nt) {
                        mma_bf16(accc[nt], aH, bH[nt]);
                        mma_bf16(accc[nt], aH, bL[nt]);
                        mma_bf16(accc[nt], aL, bH[nt]);
                    }
                }
            }

            if (i < NCH - 1) {
                int nb = buf ^ 1;
                #pragma unroll
                for (int q = 0; q < 2; ++q) {
                    uint2 hh, ll;
                    split4(v[q], hh, ll);
                    *(uint2*)(sm + CA(0, nb) + cgp*80 + (cgk + q*4)*2) = hh;
                    *(uint2*)(sm + CA(1, nb) + cgp*80 + (cgk + q*4)*2) = ll;
                }
                cp_wait0();
            }
            __syncthreads();
        }

        // scatter conv result
        {
            int r0 = mt*16 + (lane >> 2);
            int c0 = npair*16 + (lane & 3)*2;
            #pragma unroll
            for (int nt = 0; nt < 2; ++nt) {
                int c = c0 + nt*8;
                so[r0][c]       = accc[nt][0];
                so[r0][c+1]     = accc[nt][1];
                so[r0 + 8][c]   = accc[nt][2];
                so[r0 + 8][c+1] = accc[nt][3];
            }
        }
        __syncthreads();
    }

    // ======================= PHASE 2: param build (128 pixels) =====================
    if (tid < 128) {
        float ov[27];
        #pragma unroll
        for (int oc = 0; oc < 27; ++oc) ov[oc] = so[tid][oc] + ob[oc];

        int w    = tid & 63;
        int hloc = 2*hp + (tid >> 6);
        #pragma unroll
        for (int kk = 0; kk < 9; ++kk) {
            float dy = ov[2*kk];
            float dx = ov[2*kk + 1];
            float m  = 1.0f / (1.0f + expf(-ov[18 + kk]));
            int ki = kk / 3, kj = kk % 3;
            float py = (float)(hloc - 1 + ki) + dy;
            float px = (float)(w - 1 + kj) + dx;
            float fy = floorf(py), fx = floorf(px);
            float wy = py - fy,    wx = px - fx;
            int y0 = (int)fy, x0 = (int)fx;
            int y1 = y0 + 1,  x1 = x0 + 1;

            bool vy0 = (y0 >= 0) && (y0 < HH);
            bool vy1 = (y1 >= 0) && (y1 < HH);
            bool vx0 = (x0 >= 0) && (x0 < WWD);
            bool vx1 = (x1 >= 0) && (x1 < WWD);

            float w00 = (1.0f - wy) * (1.0f - wx) * m * ((vy0 && vx0) ? 1.0f : 0.0f);
            float w01 = (1.0f - wy) * wx          * m * ((vy0 && vx1) ? 1.0f : 0.0f);
            float w10 = wy * (1.0f - wx)          * m * ((vy1 && vx0) ? 1.0f : 0.0f);
            float w11 = wy * wx                   * m * ((vy1 && vx1) ? 1.0f : 0.0f);

            int yc0 = min(max(y0, 0), HH - 1);
            int yc1 = min(max(y1, 0), HH - 1);
            int xc0 = min(max(x0, 0), WWD - 1);
            int xc1 = min(max(x1, 0), WWD - 1);

            spw[kk*128 + tid] = make_float4(w00, w01, w10, w11);
            spo[kk*128 + tid] = make_int4((yc0*WWD + xc0)*CI, (yc0*WWD + xc1)*CI,
                                          (yc1*WWD + xc0)*CI, (yc1*WWD + xc1)*CI);
        }
    }
    __syncthreads();

    // ======================= PHASE 3: main GEMM, two 64-pixel passes ===============
    int mh = (wid & 1) * 32;
    int ns = (wid >> 1) * 32;
    int gp = tid >> 3;
    int gk = (tid & 7) * 4;
    int br  = tid >> 4;
    int bsg = (tid & 15) * 32;

    #pragma unroll 1
    for (int pass = 0; pass < 2; ++pass) {
        int pb = pass * 64;           // pixel base within the 128-pixel block

        float acc[2][4][4];
        #pragma unroll
        for (int i = 0; i < 2; ++i)
            #pragma unroll
            for (int j = 0; j < 4; ++j)
                #pragma unroll
                for (int q = 0; q < 4; ++q) acc[i][j][q] = 0.0f;

        // prologue chunk 0
        {
            float4 wv = spw[pb + gp];
            int4   po = spo[pb + gp];
            const float* base = xb + gk;
            float4 v0 = *(const float4*)(base + po.x);
            float4 v1 = *(const float4*)(base + po.y);
            float4 v2 = *(const float4*)(base + po.z);
            float4 v3 = *(const float4*)(base + po.w);
            const char* srcb = (const char*)g_Bh16 + (size_t)br*512 + bsg;
            const char* srcl = (const char*)g_Bl16 + (size_t)br*512 + bsg;
            uint32_t dstb = su + FB(0,0) + br*528 + bsg;
            uint32_t dstl = su + FB(1,0) + br*528 + bsg;
            cp16u(dstb, srcb); cp16u(dstb + 16, srcb + 16);
            cp16u(dstl, srcl); cp16u(dstl + 16, srcl + 16);
            cp_commit();
            float4 s;
            s.x = wv.x*v0.x + wv.y*v1.x + wv.z*v2.x + wv.w*v3.x;
            s.y = wv.x*v0.y + wv.y*v1.y + wv.z*v2.y + wv.w*v3.y;
            s.z = wv.x*v0.z + wv.y*v1.z + wv.z*v2.z + wv.w*v3.z;
            s.w = wv.x*v0.w + wv.y*v1.w + wv.z*v2.w + wv.w*v3.w;
            uint2 hh, ll;
            split4(s, hh, ll);
            *(uint2*)(sm + FA(0,0) + gp*80 + gk*2) = hh;
            *(uint2*)(sm + FA(1,0) + gp*80 + gk*2) = ll;
            cp_wait0();
        }
        __syncthreads();

        #pragma unroll 1
        for (int i = 0; i < NCH; ++i) {
            int buf = i & 1;

            float4 v0, v1, v2, v3;
            float4 wv;
            if (i < NCH - 1) {
                int sn = i + 1;
                int t = sn >> 3;
                int4 po = spo[t*128 + pb + gp];
                wv = spw[t*128 + pb + gp];
                const float* base = xb + (sn & 7)*32 + gk;
                v0 = *(const float4*)(base + po.x);
                v1 = *(const float4*)(base + po.y);
                v2 = *(const float4*)(base + po.z);
                v3 = *(const float4*)(base + po.w);
                const char* srcb = (const char*)g_Bh16 + ((size_t)sn*8192 + br*256)*2 + bsg;
                const char* srcl = (const char*)g_Bl16 + ((size_t)sn*8192 + br*256)*2 + bsg;
                uint32_t dstb = su + FB(0, buf^1) + br*528 + bsg;
                uint32_t dstl = su + FB(1, buf^1) + br*528 + bsg;
                cp16u(dstb, srcb); cp16u(dstb + 16, srcb + 16);
                cp16u(dstl, srcl); cp16u(dstl + 16, srcl + 16);
                cp_commit();
            }

            uint32_t baseAh = su + FA(0, buf) + (mh + a_row)*80 + a_cb;
            uint32_t baseAl = su + FA(1, buf) + (mh + a_row)*80 + a_cb;
            uint32_t baseBh = su + FB(0, buf) + b_krow*528 + ns*2 + b_cb;
            uint32_t baseBl = su + FB(1, buf) + b_krow*528 + ns*2 + b_cb;
            #pragma unroll
            for (int ks = 0; ks < 2; ++ks) {
                uint32_t aH[2][4], aL[2][4];
                ldm_x4(aH[0], baseAh + ks*32);
                ldm_x4(aH[1], baseAh + 1280 + ks*32);
                ldm_x4(aL[0], baseAl + ks*32);
                ldm_x4(aL[1], baseAl + 1280 + ks*32);
                uint32_t bH[4][2], bL[4][2], t4[4];
                ldm_x4t(t4, baseBh + ks*8448);
                bH[0][0]=t4[0]; bH[0][1]=t4[1]; bH[1][0]=t4[2]; bH[1][1]=t4[3];
                ldm_x4t(t4, baseBh + ks*8448 + 32);
                bH[2][0]=t4[0]; bH[2][1]=t4[1]; bH[3][0]=t4[2]; bH[3][1]=t4[3];
                ldm_x4t(t4, baseBl + ks*8448);
                bL[0][0]=t4[0]; bL[0][1]=t4[1]; bL[1][0]=t4[2]; bL[1][1]=t4[3];
                ldm_x4t(t4, baseBl + ks*8448 + 32);
                bL[2][0]=t4[0]; bL[2][1]=t4[1]; bL[3][0]=t4[2]; bL[3][1]=t4[3];
                #pragma unroll
                for (int mt = 0; mt < 2; ++mt)
                    #pragma unroll
                    for (int nt = 0; nt < 4; ++nt) {
                        mma_bf16(acc[mt][nt], aH[mt], bH[nt]);
                        mma_bf16(acc[mt][nt], aH[mt], bL[nt]);
                        mma_bf16(acc[mt][nt], aL[mt], bH[nt]);
                    }
            }

            if (i < NCH - 1) {
                float4 s;
                s.x = wv.x*v0.x + wv.y*v1.x + wv.z*v2.x + wv.w*v3.x;
                s.y = wv.x*v0.y + wv.y*v1.y + wv.z*v2.y + wv.w*v3.y;
                s.z = wv.x*v0.z + wv.y*v1.z + wv.z*v2.z + wv.w*v3.z;
                s.w = wv.x*v0.w + wv.y*v1.w + wv.z*v2.w + wv.w*v3.w;
                uint2 hh, ll;
                split4(s, hh, ll);
                *(uint2*)(sm + FA(0, buf^1) + gp*80 + gk*2) = hh;
                *(uint2*)(sm + FA(1, buf^1) + gp*80 + gk*2) = ll;
                cp_wait0();
            }
            __syncthreads();
        }

        // epilogue
        {
            float* op = out + ((size_t)(b*CO))*HWSZ + hw0 + pb;
            int r0 = mh + (lane >> 2);
            int c0 = ns + (lane & 3)*2;
            #pragma unroll
            for (int mt = 0; mt < 2; ++mt) {
                int r = r0 + mt*16;
                #pragma unroll
                for (int nt = 0; nt < 4; ++nt) {
                    int c = c0 + nt*8;
                    op[(size_t)c*HWSZ + r]           = acc[mt][nt][0];
                    op[(size_t)(c+1)*HWSZ + r]       = acc[mt][nt][1];
                    op[(size_t)c*HWSZ + r + 8]       = acc[mt][nt][2];
                    op[(size_t)(c+1)*HWSZ + r + 8]   = acc[mt][nt][3];
                }
            }
        }
        __syncthreads();
    }
}

// ---------------- launch ----------------
extern "C" void kernel_launch(void* const* d_in, const int* in_sizes, int n_in,
                              void* d_out, int out_size) {
    (void)in_sizes; (void)n_in; (void)out_size;
    const float* x  = (const float*)d_in[0];   // (4,256,64,64)
    const float* ow = (const float*)d_in[1];   // (27,256,3,3)
    const float* ob = (const float*)d_in[2];   // (27,)
    const float* dw = (const float*)d_in[3];   // (256,256,3,3)
    float* out = (float*)d_out;                // (4,256,64,64)

    cudaFuncSetAttribute(k_fused, cudaFuncAttributeMaxDynamicSharedMemorySize, FSM_TOTAL);

    dim3 tb(32, 8);
    dim3 tg(HWSZ/32, CI/32, BB);
    k_transpose_x<<<tg, tb>>>(x);
    k_prep_b<<<(NCH*8192 + 255)/256, 256>>>(dw);
    k_prep_ob<<<(NCH*1024 + 255)/256, 256>>>(ow);
    k_fused<<<128, 512, FSM_TOTAL>>>(out, ob);
}